// round 1
// baseline (speedup 1.0000x reference)
#include <cuda_runtime.h>
#include <math.h>

// ---------------- problem constants ----------------
#define NN 50000      // nodes
#define NB 128        // graphs / batch
#define NH 10         // heads
#define FD 78         // per-head feature
#define CC 780        // NH*FD
#define E0MAX 150000
#define EMAX  (E0MAX + NN)   // edges incl self loops

// ---------------- scratch (device globals; no allocs) ----------------
__device__ float g_bufA[NN * CC];   // h = x@W_gat, later hg = relu(gat)@W_gcn
__device__ float g_bufB[NN * CC];   // gat_out (bias+agg), later gcn_out (bias+agg)
__device__ float g_as[NN * NH];
__device__ float g_ad[NN * NH];
__device__ float g_e[EMAX * NH];    // e, then ex
__device__ float g_m[NN * NH];
__device__ float g_s[NN * NH];
__device__ float g_deg[NN];
__device__ float g_dinv[NN];
__device__ float g_cnt[NB];
__device__ float g_gmx[NB * CC];
__device__ float g_gav[NB * CC];
__device__ float g_g[NB * 1560];
__device__ float g_t1[NB * 1500];
__device__ float g_xc[NB * 384];
__device__ float g_xt2c[NB * 3872];
__device__ float g_xt1c[NB * 544];
__device__ float g_f1[NB * 1024];
__device__ float g_f2[NB * 512];

// ---------------- helpers ----------------
__device__ __forceinline__ void edge_sd(const int* ei, int E0, int e, int& s, int& d) {
    if (e < E0) { s = ei[e]; d = ei[E0 + e]; }
    else        { s = e - E0; d = e - E0; }
}

__device__ __forceinline__ void atomicMaxF(float* addr, float val) {
    int* ai = (int*)addr;
    int old = *ai;
    while (__int_as_float(old) < val) {
        int prev = atomicCAS(ai, old, __float_as_int(val));
        if (prev == old) break;
        old = prev;
    }
}

// ---------------- generic tiled SGEMM: C[M,N] = op(A[M,K]) @ B[K,N] + bias ----------------
// ldc allows writing into a strided slice (for concat outputs).
template<bool RELU_OUT, bool RELU_A>
__global__ void sgemm_kernel(const float* __restrict__ A, const float* __restrict__ B,
                             const float* __restrict__ bias, float* __restrict__ C,
                             int M, int N, int K, int ldc)
{
    const int BM = 64, BN = 64, BK = 16;
    __shared__ float As[BK][BM + 1];
    __shared__ float Bs[BK][BN + 1];
    int tid = threadIdx.x;            // 256 threads
    int tx = tid & 15, ty = tid >> 4;
    int brow = blockIdx.y * BM;
    int bcol = blockIdx.x * BN;

    float acc[4][4];
    #pragma unroll
    for (int i = 0; i < 4; i++)
        #pragma unroll
        for (int j = 0; j < 4; j++) acc[i][j] = 0.f;

    for (int k0 = 0; k0 < K; k0 += BK) {
        #pragma unroll
        for (int i = 0; i < 4; i++) {
            int idx = tid + i * 256;          // 0..1023 over (m,k)
            int m = idx >> 4;                 // /16
            int k = idx & 15;
            int gm = brow + m, gk = k0 + k;
            float v = (gm < M && gk < K) ? A[(size_t)gm * K + gk] : 0.f;
            if (RELU_A) v = fmaxf(v, 0.f);
            As[k][m] = v;
        }
        #pragma unroll
        for (int i = 0; i < 4; i++) {
            int idx = tid + i * 256;          // over (k,n)
            int k = idx >> 6;                 // /64
            int n = idx & 63;
            int gk = k0 + k, gn = bcol + n;
            Bs[k][n] = (gk < K && gn < N) ? B[(size_t)gk * N + gn] : 0.f;
        }
        __syncthreads();
        #pragma unroll
        for (int kk = 0; kk < BK; kk++) {
            float a[4], b[4];
            #pragma unroll
            for (int i = 0; i < 4; i++) a[i] = As[kk][ty * 4 + i];
            #pragma unroll
            for (int j = 0; j < 4; j++) b[j] = Bs[kk][tx * 4 + j];
            #pragma unroll
            for (int i = 0; i < 4; i++)
                #pragma unroll
                for (int j = 0; j < 4; j++) acc[i][j] += a[i] * b[j];
        }
        __syncthreads();
    }
    #pragma unroll
    for (int i = 0; i < 4; i++) {
        int gm = brow + ty * 4 + i;
        if (gm >= M) continue;
        #pragma unroll
        for (int j = 0; j < 4; j++) {
            int gn = bcol + tx * 4 + j;
            if (gn >= N) continue;
            float v = acc[i][j] + (bias ? bias[gn] : 0.f);
            if (RELU_OUT) v = fmaxf(v, 0.f);
            C[(size_t)gm * ldc + gn] = v;
        }
    }
}

// ---------------- small kernels ----------------
__global__ void k_init() {
    int i = blockIdx.x * blockDim.x + threadIdx.x;
    if (i < NN * NH) { g_m[i] = __int_as_float(0xff800000); g_s[i] = 0.f; }
    if (i < NN) g_deg[i] = 0.f;
    if (i < NB) g_cnt[i] = 0.f;
    if (i < NB * CC) { g_gmx[i] = 0.f; g_gav[i] = 0.f; }
}

__global__ void k_fill_bias_B(const float* __restrict__ bias) {
    int i = blockIdx.x * blockDim.x + threadIdx.x;
    if (i < NN * CC) g_bufB[i] = bias[i % CC];
}

__global__ void k_compute_a(const float* __restrict__ att_src, const float* __restrict__ att_dst) {
    int i = blockIdx.x * blockDim.x + threadIdx.x;
    if (i >= NN * NH) return;
    int n = i / NH, h = i % NH;
    const float* hp = &g_bufA[(size_t)n * CC + h * FD];
    const float* ws = &att_src[h * FD];
    const float* wd = &att_dst[h * FD];
    float s = 0.f, d = 0.f;
    #pragma unroll 6
    for (int f = 0; f < FD; f++) { float v = hp[f]; s += v * ws[f]; d += v * wd[f]; }
    g_as[i] = s;
    g_ad[i] = d;
}

__global__ void k_edge_e(const int* __restrict__ ei, int E0, int E) {
    int e = blockIdx.x * blockDim.x + threadIdx.x;
    if (e >= E) return;
    int s, d; edge_sd(ei, E0, e, s, d);
    atomicAdd(&g_deg[d], 1.f);
    #pragma unroll
    for (int h = 0; h < NH; h++) {
        float t = g_as[s * NH + h] + g_ad[d * NH + h];
        t = (t > 0.f) ? t : 0.2f * t;
        g_e[(size_t)e * NH + h] = t;
        atomicMaxF(&g_m[d * NH + h], t);
    }
}

__global__ void k_edge_softmax(const int* __restrict__ ei, int E0, int E) {
    int e = blockIdx.x * blockDim.x + threadIdx.x;
    if (e >= E) return;
    int s, d; edge_sd(ei, E0, e, s, d);
    (void)s;
    #pragma unroll
    for (int h = 0; h < NH; h++) {
        float ex = expf(g_e[(size_t)e * NH + h] - g_m[d * NH + h]);
        g_e[(size_t)e * NH + h] = ex;
        atomicAdd(&g_s[d * NH + h], ex);
    }
}

__global__ void k_gat_agg(const int* __restrict__ ei, int E0) {
    int e = blockIdx.x;
    int s, d; edge_sd(ei, E0, e, s, d);
    __shared__ float sal[NH];
    if (threadIdx.x < NH)
        sal[threadIdx.x] = g_e[(size_t)e * NH + threadIdx.x] /
                           (g_s[d * NH + threadIdx.x] + 1e-16f);
    __syncthreads();
    for (int f = threadIdx.x; f < CC; f += blockDim.x)
        atomicAdd(&g_bufB[(size_t)d * CC + f], g_bufA[(size_t)s * CC + f] * sal[f / FD]);
}

__global__ void k_node_dinv_cnt(const int* __restrict__ batch) {
    int n = blockIdx.x * blockDim.x + threadIdx.x;
    if (n >= NN) return;
    float dg = g_deg[n];
    g_dinv[n] = (dg > 0.f) ? rsqrtf(dg) : 0.f;
    atomicAdd(&g_cnt[batch[n]], 1.f);
}

__global__ void k_gcn_agg(const int* __restrict__ ei, int E0) {
    int e = blockIdx.x;
    int s, d; edge_sd(ei, E0, e, s, d);
    float norm = g_dinv[s] * g_dinv[d];
    for (int f = threadIdx.x; f < CC; f += blockDim.x)
        atomicAdd(&g_bufB[(size_t)d * CC + f], g_bufA[(size_t)s * CC + f] * norm);
}

__global__ void k_pool(const int* __restrict__ batch) {
    int i = blockIdx.x * blockDim.x + threadIdx.x;
    if (i >= NN * CC) return;
    int n = i / CC, f = i % CC;
    int b = batch[n];
    float v = fmaxf(g_bufB[i], 0.f);           // relu(gcn_out)
    atomicMax((int*)&g_gmx[b * CC + f], __float_as_int(v));  // v >= 0, int cmp valid
    atomicAdd(&g_gav[b * CC + f], v);
}

__global__ void k_pool_fin() {
    int i = blockIdx.x * blockDim.x + threadIdx.x;
    if (i >= NB * CC) return;
    int b = i / CC, f = i % CC;
    g_g[b * 1560 + f] = g_gmx[i];
    g_g[b * 1560 + 780 + f] = g_gav[i] / fmaxf(g_cnt[b], 1.f);
}

// conv1d on embeddings: per-vocab weight aggregation (exact sum reorder).
// y[b,o,l] = bc2[o] + sum_v sum_k wag[v][o][k] * emb[v, l+k]
__global__ void k_conv2(const int* __restrict__ t2, const float* __restrict__ emb,
                        const float* __restrict__ Wc2, const float* __restrict__ bc2)
{
    __shared__ float wag[26 * 256];   // [v][o*8+k]
    int b = blockIdx.x;
    int tid = threadIdx.x;            // 256
    for (int v = 0; v < 26; v++) wag[v * 256 + tid] = 0.f;
    __syncthreads();
    int o = tid >> 3, k = tid & 7;
    const float* wcol = &Wc2[o * 8000 + k];
    const int* t2b = &t2[b * 1000];
    for (int i = 0; i < 1000; i++) {
        int v = t2b[i];
        wag[v * 256 + tid] += wcol[i * 8];
    }
    __syncthreads();
    for (int j = tid; j < 32 * 121; j += 256) {
        int oo = j / 121, l = j % 121;
        float acc = bc2[oo];
        for (int v = 0; v < 26; v++) {
            const float* wa = &wag[v * 256 + oo * 8];
            const float* er = &emb[v * 128 + l];
            #pragma unroll
            for (int kk = 0; kk < 8; kk++) acc += wa[kk] * er[kk];
        }
        g_xt2c[b * 3872 + j] = acc;
    }
}

__global__ void k_conv1(const float* __restrict__ t1, const float* __restrict__ Wc1,
                        const float* __restrict__ bc1)
{
    int b = blockIdx.x;
    int tid = threadIdx.x;            // 544 = 32*17
    int o = tid / 17, l = tid % 17;
    float acc = bc1[o];
    for (int i = 0; i < 20; i++) {
        const float* xr = &t1[b * 480 + i * 24 + l];
        const float* wr = &Wc1[o * 160 + i * 8];
        #pragma unroll
        for (int k = 0; k < 8; k++) acc += xr[k] * wr[k];
    }
    g_xt1c[b * 544 + tid] = acc;
}

// ---------------- launch ----------------
static inline dim3 gemm_grid(int M, int N) {
    return dim3((N + 63) / 64, (M + 63) / 64);
}

extern "C" void kernel_launch(void* const* d_in, const int* in_sizes, int n_in,
                              void* d_out, int out_size)
{
    const float* x       = (const float*)d_in[0];
    const int*   ei      = (const int*)  d_in[1];
    const int*   batch   = (const int*)  d_in[2];
    const float* target1 = (const float*)d_in[3];
    const int*   target2 = (const int*)  d_in[4];
    const float* W_gat   = (const float*)d_in[5];
    const float* att_src = (const float*)d_in[6];
    const float* att_dst = (const float*)d_in[7];
    const float* b_gat   = (const float*)d_in[8];
    const float* W_gcn   = (const float*)d_in[9];
    const float* b_gcn   = (const float*)d_in[10];
    const float* W_fcg1  = (const float*)d_in[11];
    const float* b_fcg1  = (const float*)d_in[12];
    const float* W_fcg2  = (const float*)d_in[13];
    const float* b_fcg2  = (const float*)d_in[14];
    const float* emb     = (const float*)d_in[15];
    const float* Wc2     = (const float*)d_in[16];
    const float* bc2     = (const float*)d_in[17];
    const float* W_fc2xt = (const float*)d_in[18];
    const float* b_fc2xt = (const float*)d_in[19];
    const float* Wc1     = (const float*)d_in[20];
    const float* bc1     = (const float*)d_in[21];
    const float* W_fc1xt = (const float*)d_in[22];
    const float* b_fc1xt = (const float*)d_in[23];
    const float* W_fc1   = (const float*)d_in[24];
    const float* b_fc1   = (const float*)d_in[25];
    const float* W_fc2   = (const float*)d_in[26];
    const float* b_fc2   = (const float*)d_in[27];
    const float* W_out   = (const float*)d_in[28];
    const float* b_out   = (const float*)d_in[29];
    float* out = (float*)d_out;

    int E0 = in_sizes[1] / 2;           // 150000
    int E  = E0 + NN;                   // + self loops

    float *bufA, *bufB, *pg, *pt1, *pxc, *pxt2c, *pxt1c, *pf1, *pf2;
    cudaGetSymbolAddress((void**)&bufA,  g_bufA);
    cudaGetSymbolAddress((void**)&bufB,  g_bufB);
    cudaGetSymbolAddress((void**)&pg,    g_g);
    cudaGetSymbolAddress((void**)&pt1,   g_t1);
    cudaGetSymbolAddress((void**)&pxc,   g_xc);
    cudaGetSymbolAddress((void**)&pxt2c, g_xt2c);
    cudaGetSymbolAddress((void**)&pxt1c, g_xt1c);
    cudaGetSymbolAddress((void**)&pf1,   g_f1);
    cudaGetSymbolAddress((void**)&pf2,   g_f2);

    // 0) init accumulators
    k_init<<<(NN * NH + 255) / 256, 256>>>();

    // 1) h = x @ W_gat    [50000,78]@[78,780]
    sgemm_kernel<false, false><<<gemm_grid(NN, CC), 256>>>(x, W_gat, nullptr, bufA, NN, CC, FD, CC);

    // 2) attention logits per node/head
    k_compute_a<<<(NN * NH + 255) / 256, 256>>>(att_src, att_dst);

    // 3) edge e + segment max + deg
    k_edge_e<<<(E + 255) / 256, 256>>>(ei, E0, E);

    // 4) exp + segment sum
    k_edge_softmax<<<(E + 255) / 256, 256>>>(ei, E0, E);

    // 5) gat_out = bias, then scatter-add messages
    k_fill_bias_B<<<(NN * CC + 255) / 256, 256>>>(b_gat);
    k_gat_agg<<<E, 256>>>(ei, E0);

    // 6) dinv + graph node counts
    k_node_dinv_cnt<<<(NN + 255) / 256, 256>>>(batch);

    // 7) hg = relu(gat_out) @ W_gcn    [50000,780]@[780,780]  (dominant GEMM)
    sgemm_kernel<false, true><<<gemm_grid(NN, CC), 256>>>(bufB, W_gcn, nullptr, bufA, NN, CC, CC, CC);

    // 8) gcn_out = bias, scatter-add normalized messages
    k_fill_bias_B<<<(NN * CC + 255) / 256, 256>>>(b_gcn);
    k_gcn_agg<<<E, 256>>>(ei, E0);

    // 9) relu + global max/mean pool
    k_pool<<<(NN * CC + 255) / 256, 256>>>(batch);
    k_pool_fin<<<(NB * CC + 255) / 256, 256>>>();

    // 10) graph MLP head
    sgemm_kernel<true,  false><<<gemm_grid(NB, 1500), 256>>>(pg,  W_fcg1, b_fcg1, pt1, NB, 1500, 1560, 1500);
    sgemm_kernel<false, false><<<gemm_grid(NB, 128),  256>>>(pt1, W_fcg2, b_fcg2, pxc + 0,   NB, 128, 1500, 384);

    // 11) protein branches
    k_conv2<<<NB, 256>>>(target2, emb, Wc2, bc2);
    sgemm_kernel<false, false><<<gemm_grid(NB, 128),  256>>>(pxt2c, W_fc2xt, b_fc2xt, pxc + 256, NB, 128, 3872, 384);
    k_conv1<<<NB, 544>>>(target1, Wc1, bc1);
    sgemm_kernel<false, false><<<gemm_grid(NB, 128),  256>>>(pxt1c, W_fc1xt, b_fc1xt, pxc + 128, NB, 128, 544, 384);

    // 12) final MLP
    sgemm_kernel<true,  false><<<gemm_grid(NB, 1024), 256>>>(pxc, W_fc1, b_fc1, pf1, NB, 1024, 384, 1024);
    sgemm_kernel<true,  false><<<gemm_grid(NB, 512),  256>>>(pf1, W_fc2, b_fc2, pf2, NB, 512, 1024, 512);
    sgemm_kernel<false, false><<<gemm_grid(NB, 1),    256>>>(pf2, W_out, b_out, out, NB, 1, 512, 1);
}

// round 2
// speedup vs baseline: 1.1047x; 1.1047x over previous
#include <cuda_runtime.h>
#include <cuda_bf16.h>
#include <mma.h>
#include <math.h>

using namespace nvcuda;

// ---------------- problem constants ----------------
#define NN 50000      // nodes
#define NB 128        // graphs / batch
#define NH 10         // heads
#define FD 78         // per-head feature
#define CC 780        // NH*FD
#define E0MAX 150000
#define EMAX  (E0MAX + NN)   // edges incl self loops
#define KP2 784              // 780 padded to mult of 16
#define KP1 80               // 78 padded to mult of 16

// ---------------- scratch (device globals; no allocs) ----------------
__device__ float g_bufA[NN * CC];   // h = x@W_gat, later hg = relu(gat)@W_gcn
__device__ float g_bufB[NN * CC];   // gat_out (bias+agg), later gcn_out (bias+agg)
__device__ __nv_bfloat16 g_Ah[NN * KP2];
__device__ __nv_bfloat16 g_Al[NN * KP2];
__device__ __nv_bfloat16 g_Bh[KP2 * CC];
__device__ __nv_bfloat16 g_Bl[KP2 * CC];
__device__ float g_as[NN * NH];
__device__ float g_ad[NN * NH];
__device__ float g_e[EMAX * NH];    // e, then ex
__device__ unsigned g_menc[NN * NH];
__device__ float g_s[NN * NH];
__device__ float g_deg[NN];
__device__ float g_dinv[NN];
__device__ float g_cnt[NB];
__device__ float g_gmx[NB * CC];
__device__ float g_gav[NB * CC];
__device__ float g_g[NB * 1560];
__device__ float g_t1[NB * 1500];
__device__ float g_xc[NB * 384];
__device__ float g_xt2c[NB * 3872];
__device__ float g_xt1c[NB * 544];
__device__ float g_f1[NB * 1024];
__device__ float g_f2[NB * 512];

// ---------------- helpers ----------------
__device__ __forceinline__ void edge_sd(const int* ei, int E0, int e, int& s, int& d) {
    if (e < E0) { s = ei[e]; d = ei[E0 + e]; }
    else        { s = e - E0; d = e - E0; }
}

// monotone float<->uint encoding for atomicMax on floats
__device__ __forceinline__ unsigned fenc(float f) {
    unsigned b = __float_as_uint(f);
    return (b & 0x80000000u) ? ~b : (b | 0x80000000u);
}
__device__ __forceinline__ float fdec(unsigned e) {
    unsigned b = (e & 0x80000000u) ? (e & 0x7fffffffu) : ~e;
    return __uint_as_float(b);
}

// ---------------- split-bf16 conversion kernels ----------------
template<bool RELU>
__global__ void k_convA(const float* __restrict__ src, int M, int K, int Kp,
                        __nv_bfloat16* __restrict__ Ah, __nv_bfloat16* __restrict__ Al)
{
    size_t idx = (size_t)blockIdx.x * blockDim.x + threadIdx.x;
    if (idx >= (size_t)M * Kp) return;
    int c = (int)(idx % Kp);
    int r = (int)(idx / Kp);
    float v = 0.f;
    if (c < K) {
        v = src[(size_t)r * K + c];
        if (RELU) v = fmaxf(v, 0.f);
    }
    __nv_bfloat16 h = __float2bfloat16(v);
    Ah[idx] = h;
    Al[idx] = __float2bfloat16(v - __bfloat162float(h));
}

__global__ void k_convB(const float* __restrict__ W, int K, int N, int Kp,
                        __nv_bfloat16* __restrict__ Bh, __nv_bfloat16* __restrict__ Bl)
{
    size_t idx = (size_t)blockIdx.x * blockDim.x + threadIdx.x;
    if (idx >= (size_t)Kp * N) return;
    int n = (int)(idx % N);
    int k = (int)(idx / N);
    float v = (k < K) ? W[(size_t)k * N + n] : 0.f;
    __nv_bfloat16 h = __float2bfloat16(v);
    Bh[idx] = h;
    Bl[idx] = __float2bfloat16(v - __bfloat162float(h));
}

// ---------------- split-bf16 wmma GEMM: C = A @ B (fp32 accurate) ----------------
// A: [M, Kp] bf16 hi/lo row-major, B: [Kp, N] bf16 hi/lo row-major, C fp32 ld=ldc
// block tile 128x128, 8 warps (4M x 2N), warp tile 32x64, BK=16
__global__ __launch_bounds__(256)
void wmma_gemm(const __nv_bfloat16* __restrict__ Ah, const __nv_bfloat16* __restrict__ Al,
               const __nv_bfloat16* __restrict__ Bh, const __nv_bfloat16* __restrict__ Bl,
               float* __restrict__ C, int M, int N, int Kp, int ldc)
{
    __shared__ __align__(16) __nv_bfloat16 AsH[128][16];
    __shared__ __align__(16) __nv_bfloat16 AsL[128][16];
    __shared__ __align__(16) __nv_bfloat16 BsH[16][128];
    __shared__ __align__(16) __nv_bfloat16 BsL[16][128];
    __shared__ __align__(16) float stage[8][16][16];

    int tid = threadIdx.x;
    int wid = tid >> 5, lane = tid & 31;
    int wm = wid & 3, wn = wid >> 2;
    int brow = blockIdx.y * 128, bcol = blockIdx.x * 128;

    wmma::fragment<wmma::accumulator, 16, 16, 16, float> acc[2][4];
    #pragma unroll
    for (int i = 0; i < 2; i++)
        #pragma unroll
        for (int j = 0; j < 4; j++) wmma::fill_fragment(acc[i][j], 0.f);

    const bool fullN = (bcol + 128 <= N);

    for (int k0 = 0; k0 < Kp; k0 += 16) {
        // A tile: 128 rows x 16 cols, uint4 (8 bf16) per load, 2 loads/thread
        {
            int row = tid >> 1, seg = tid & 1;
            int gm = brow + row;
            uint4 vh = make_uint4(0, 0, 0, 0), vl = vh;
            if (gm < M) {
                const uint4* ph = (const uint4*)(Ah + (size_t)gm * Kp + k0);
                const uint4* pl = (const uint4*)(Al + (size_t)gm * Kp + k0);
                vh = ph[seg]; vl = pl[seg];
            }
            ((uint4*)&AsH[row][0])[seg] = vh;
            ((uint4*)&AsL[row][0])[seg] = vl;
        }
        // B tile: 16 rows x 128 cols
        if (fullN) {
            int k = tid >> 4, cs = tid & 15;
            size_t base = (size_t)(k0 + k) * N + bcol + cs * 8;
            const uint2* ph = (const uint2*)(Bh + base);
            const uint2* pl = (const uint2*)(Bl + base);
            uint2 h0 = ph[0], h1 = ph[1];
            uint2 l0 = pl[0], l1 = pl[1];
            uint2* dh = (uint2*)&BsH[k][cs * 8];
            uint2* dl = (uint2*)&BsL[k][cs * 8];
            dh[0] = h0; dh[1] = h1;
            dl[0] = l0; dl[1] = l1;
        } else {
            __nv_bfloat16 z = __float2bfloat16(0.f);
            for (int idx = tid; idx < 16 * 128; idx += 256) {
                int k = idx >> 7, c = idx & 127;
                int gn = bcol + c;
                __nv_bfloat16 vh = z, vl = z;
                if (gn < N) {
                    size_t o = (size_t)(k0 + k) * N + gn;
                    vh = Bh[o]; vl = Bl[o];
                }
                BsH[k][c] = vh; BsL[k][c] = vl;
            }
        }
        __syncthreads();

        wmma::fragment<wmma::matrix_a, 16, 16, 16, __nv_bfloat16, wmma::row_major> ah[2], al[2];
        wmma::fragment<wmma::matrix_b, 16, 16, 16, __nv_bfloat16, wmma::row_major> bh[4], bl[4];
        #pragma unroll
        for (int i = 0; i < 2; i++) {
            wmma::load_matrix_sync(ah[i], &AsH[wm * 32 + i * 16][0], 16);
            wmma::load_matrix_sync(al[i], &AsL[wm * 32 + i * 16][0], 16);
        }
        #pragma unroll
        for (int j = 0; j < 4; j++) {
            wmma::load_matrix_sync(bh[j], &BsH[0][wn * 64 + j * 16], 128);
            wmma::load_matrix_sync(bl[j], &BsL[0][wn * 64 + j * 16], 128);
        }
        #pragma unroll
        for (int i = 0; i < 2; i++)
            #pragma unroll
            for (int j = 0; j < 4; j++) {
                wmma::mma_sync(acc[i][j], ah[i], bh[j], acc[i][j]);
                wmma::mma_sync(acc[i][j], ah[i], bl[j], acc[i][j]);
                wmma::mma_sync(acc[i][j], al[i], bh[j], acc[i][j]);
            }
        __syncthreads();
    }

    // store via per-warp staging (handles partial M/N tiles)
    #pragma unroll
    for (int i = 0; i < 2; i++)
        #pragma unroll
        for (int j = 0; j < 4; j++) {
            wmma::store_matrix_sync(&stage[wid][0][0], acc[i][j], 16, wmma::mem_row_major);
            __syncwarp();
            int gm0 = brow + wm * 32 + i * 16;
            int gn0 = bcol + wn * 64 + j * 16;
            for (int e = lane; e < 256; e += 32) {
                int r = e >> 4, c = e & 15;
                int gm = gm0 + r, gn = gn0 + c;
                if (gm < M && gn < N) C[(size_t)gm * ldc + gn] = stage[wid][r][c];
            }
            __syncwarp();
        }
}

// ---------------- fp32 tiled SGEMM for the small FC head ----------------
template<bool RELU_OUT>
__global__ void sgemm_kernel(const float* __restrict__ A, const float* __restrict__ B,
                             const float* __restrict__ bias, float* __restrict__ C,
                             int M, int N, int K, int ldc)
{
    const int BM = 64, BN = 64, BK = 16;
    __shared__ float As[BK][BM + 1];
    __shared__ float Bs[BK][BN + 1];
    int tid = threadIdx.x;
    int tx = tid & 15, ty = tid >> 4;
    int brow = blockIdx.y * BM;
    int bcol = blockIdx.x * BN;

    float acc[4][4];
    #pragma unroll
    for (int i = 0; i < 4; i++)
        #pragma unroll
        for (int j = 0; j < 4; j++) acc[i][j] = 0.f;

    for (int k0 = 0; k0 < K; k0 += BK) {
        #pragma unroll
        for (int i = 0; i < 4; i++) {
            int idx = tid + i * 256;
            int m = idx >> 4, k = idx & 15;
            int gm = brow + m, gk = k0 + k;
            As[k][m] = (gm < M && gk < K) ? A[(size_t)gm * K + gk] : 0.f;
        }
        #pragma unroll
        for (int i = 0; i < 4; i++) {
            int idx = tid + i * 256;
            int k = idx >> 6, n = idx & 63;
            int gk = k0 + k, gn = bcol + n;
            Bs[k][n] = (gk < K && gn < N) ? B[(size_t)gk * N + gn] : 0.f;
        }
        __syncthreads();
        #pragma unroll
        for (int kk = 0; kk < BK; kk++) {
            float a[4], b[4];
            #pragma unroll
            for (int i = 0; i < 4; i++) a[i] = As[kk][ty * 4 + i];
            #pragma unroll
            for (int j = 0; j < 4; j++) b[j] = Bs[kk][tx * 4 + j];
            #pragma unroll
            for (int i = 0; i < 4; i++)
                #pragma unroll
                for (int j = 0; j < 4; j++) acc[i][j] += a[i] * b[j];
        }
        __syncthreads();
    }
    #pragma unroll
    for (int i = 0; i < 4; i++) {
        int gm = brow + ty * 4 + i;
        if (gm >= M) continue;
        #pragma unroll
        for (int j = 0; j < 4; j++) {
            int gn = bcol + tx * 4 + j;
            if (gn >= N) continue;
            float v = acc[i][j] + (bias ? bias[gn] : 0.f);
            if (RELU_OUT) v = fmaxf(v, 0.f);
            C[(size_t)gm * ldc + gn] = v;
        }
    }
}

// ---------------- small kernels ----------------
__global__ void k_init() {
    int i = blockIdx.x * blockDim.x + threadIdx.x;
    if (i < NN * NH) { g_menc[i] = 0u; g_s[i] = 0.f; }
    if (i < NN) g_deg[i] = 0.f;
    if (i < NB) g_cnt[i] = 0.f;
    if (i < NB * CC) { g_gmx[i] = 0.f; g_gav[i] = 0.f; }
}

__global__ void k_fill_bias_B(const float* __restrict__ bias) {
    int i = blockIdx.x * blockDim.x + threadIdx.x;
    if (i < NN * CC) g_bufB[i] = bias[i % CC];
}

__global__ void k_compute_a(const float* __restrict__ att_src, const float* __restrict__ att_dst) {
    int i = blockIdx.x * blockDim.x + threadIdx.x;
    if (i >= NN * NH) return;
    int n = i / NH, h = i % NH;
    const float* hp = &g_bufA[(size_t)n * CC + h * FD];
    const float* ws = &att_src[h * FD];
    const float* wd = &att_dst[h * FD];
    float s = 0.f, d = 0.f;
    #pragma unroll 6
    for (int f = 0; f < FD; f++) { float v = hp[f]; s += v * ws[f]; d += v * wd[f]; }
    g_as[i] = s;
    g_ad[i] = d;
}

__global__ void k_edge_e(const int* __restrict__ ei, int E0, int E) {
    int e = blockIdx.x * blockDim.x + threadIdx.x;
    if (e >= E) return;
    int s, d; edge_sd(ei, E0, e, s, d);
    atomicAdd(&g_deg[d], 1.f);
    #pragma unroll
    for (int h = 0; h < NH; h++) {
        float t = g_as[s * NH + h] + g_ad[d * NH + h];
        t = (t > 0.f) ? t : 0.2f * t;
        g_e[(size_t)e * NH + h] = t;
        atomicMax(&g_menc[d * NH + h], fenc(t));
    }
}

__global__ void k_edge_softmax(const int* __restrict__ ei, int E0, int E) {
    int e = blockIdx.x * blockDim.x + threadIdx.x;
    if (e >= E) return;
    int s, d; edge_sd(ei, E0, e, s, d);
    (void)s;
    #pragma unroll
    for (int h = 0; h < NH; h++) {
        float m = fdec(g_menc[d * NH + h]);
        float ex = expf(g_e[(size_t)e * NH + h] - m);
        g_e[(size_t)e * NH + h] = ex;
        atomicAdd(&g_s[d * NH + h], ex);
    }
}

__global__ void k_gat_agg(const int* __restrict__ ei, int E0) {
    int e = blockIdx.x;
    int s, d; edge_sd(ei, E0, e, s, d);
    __shared__ float sal[NH];
    if (threadIdx.x < NH)
        sal[threadIdx.x] = g_e[(size_t)e * NH + threadIdx.x] /
                           (g_s[d * NH + threadIdx.x] + 1e-16f);
    __syncthreads();
    for (int f = threadIdx.x; f < CC; f += blockDim.x)
        atomicAdd(&g_bufB[(size_t)d * CC + f], g_bufA[(size_t)s * CC + f] * sal[f / FD]);
}

__global__ void k_node_dinv_cnt(const int* __restrict__ batch) {
    int n = blockIdx.x * blockDim.x + threadIdx.x;
    if (n >= NN) return;
    float dg = g_deg[n];
    g_dinv[n] = (dg > 0.f) ? rsqrtf(dg) : 0.f;
    atomicAdd(&g_cnt[batch[n]], 1.f);
}

__global__ void k_gcn_agg(const int* __restrict__ ei, int E0) {
    int e = blockIdx.x;
    int s, d; edge_sd(ei, E0, e, s, d);
    float norm = g_dinv[s] * g_dinv[d];
    const float4* srcp = (const float4*)(g_bufA + (size_t)s * CC);
    float* dstp = g_bufB + (size_t)d * CC;
    for (int q = threadIdx.x; q < CC / 4; q += blockDim.x) {
        float4 v = srcp[q];
        int f = q * 4;
        atomicAdd(dstp + f + 0, v.x * norm);
        atomicAdd(dstp + f + 1, v.y * norm);
        atomicAdd(dstp + f + 2, v.z * norm);
        atomicAdd(dstp + f + 3, v.w * norm);
    }
}

__global__ void k_pool(const int* __restrict__ batch) {
    int i = blockIdx.x * blockDim.x + threadIdx.x;
    if (i >= NN * CC) return;
    int n = i / CC, f = i % CC;
    int b = batch[n];
    float v = fmaxf(g_bufB[i], 0.f);           // relu(gcn_out)
    atomicMax((int*)&g_gmx[b * CC + f], __float_as_int(v));  // v >= 0, int cmp valid
    atomicAdd(&g_gav[b * CC + f], v);
}

__global__ void k_pool_fin() {
    int i = blockIdx.x * blockDim.x + threadIdx.x;
    if (i >= NB * CC) return;
    int b = i / CC, f = i % CC;
    g_g[b * 1560 + f] = g_gmx[i];
    g_g[b * 1560 + 780 + f] = g_gav[i] / fmaxf(g_cnt[b], 1.f);
}

// conv1d on embeddings: per-vocab weight aggregation (exact sum reorder).
__global__ void k_conv2(const int* __restrict__ t2, const float* __restrict__ emb,
                        const float* __restrict__ Wc2, const float* __restrict__ bc2)
{
    __shared__ float wag[26 * 256];   // [v][o*8+k]
    int b = blockIdx.x;
    int tid = threadIdx.x;            // 256
    for (int v = 0; v < 26; v++) wag[v * 256 + tid] = 0.f;
    __syncthreads();
    int o = tid >> 3, k = tid & 7;
    const float* wcol = &Wc2[o * 8000 + k];
    const int* t2b = &t2[b * 1000];
    for (int i = 0; i < 1000; i++) {
        int v = t2b[i];
        wag[v * 256 + tid] += wcol[i * 8];
    }
    __syncthreads();
    for (int j = tid; j < 32 * 121; j += 256) {
        int oo = j / 121, l = j % 121;
        float acc = bc2[oo];
        for (int v = 0; v < 26; v++) {
            const float* wa = &wag[v * 256 + oo * 8];
            const float* er = &emb[v * 128 + l];
            #pragma unroll
            for (int kk = 0; kk < 8; kk++) acc += wa[kk] * er[kk];
        }
        g_xt2c[b * 3872 + j] = acc;
    }
}

__global__ void k_conv1(const float* __restrict__ t1, const float* __restrict__ Wc1,
                        const float* __restrict__ bc1)
{
    int b = blockIdx.x;
    int tid = threadIdx.x;            // 544 = 32*17
    int o = tid / 17, l = tid % 17;
    float acc = bc1[o];
    for (int i = 0; i < 20; i++) {
        const float* xr = &t1[b * 480 + i * 24 + l];
        const float* wr = &Wc1[o * 160 + i * 8];
        #pragma unroll
        for (int k = 0; k < 8; k++) acc += xr[k] * wr[k];
    }
    g_xt1c[b * 544 + tid] = acc;
}

// ---------------- launch ----------------
static inline dim3 gemm_grid(int M, int N) {
    return dim3((N + 63) / 64, (M + 63) / 64);
}
static inline dim3 wmma_grid(int M, int N) {
    return dim3((N + 127) / 128, (M + 127) / 128);
}

extern "C" void kernel_launch(void* const* d_in, const int* in_sizes, int n_in,
                              void* d_out, int out_size)
{
    const float* x       = (const float*)d_in[0];
    const int*   ei      = (const int*)  d_in[1];
    const int*   batch   = (const int*)  d_in[2];
    const float* target1 = (const float*)d_in[3];
    const int*   target2 = (const int*)  d_in[4];
    const float* W_gat   = (const float*)d_in[5];
    const float* att_src = (const float*)d_in[6];
    const float* att_dst = (const float*)d_in[7];
    const float* b_gat   = (const float*)d_in[8];
    const float* W_gcn   = (const float*)d_in[9];
    const float* b_gcn   = (const float*)d_in[10];
    const float* W_fcg1  = (const float*)d_in[11];
    const float* b_fcg1  = (const float*)d_in[12];
    const float* W_fcg2  = (const float*)d_in[13];
    const float* b_fcg2  = (const float*)d_in[14];
    const float* emb     = (const float*)d_in[15];
    const float* Wc2     = (const float*)d_in[16];
    const float* bc2     = (const float*)d_in[17];
    const float* W_fc2xt = (const float*)d_in[18];
    const float* b_fc2xt = (const float*)d_in[19];
    const float* Wc1     = (const float*)d_in[20];
    const float* bc1     = (const float*)d_in[21];
    const float* W_fc1xt = (const float*)d_in[22];
    const float* b_fc1xt = (const float*)d_in[23];
    const float* W_fc1   = (const float*)d_in[24];
    const float* b_fc1   = (const float*)d_in[25];
    const float* W_fc2   = (const float*)d_in[26];
    const float* b_fc2   = (const float*)d_in[27];
    const float* W_out   = (const float*)d_in[28];
    const float* b_out   = (const float*)d_in[29];
    float* out = (float*)d_out;

    int E0 = in_sizes[1] / 2;           // 150000
    int E  = E0 + NN;                   // + self loops

    float *bufA, *bufB, *pg, *pt1, *pxc, *pxt2c, *pxt1c, *pf1, *pf2;
    __nv_bfloat16 *pAh, *pAl, *pBh, *pBl;
    cudaGetSymbolAddress((void**)&bufA,  g_bufA);
    cudaGetSymbolAddress((void**)&bufB,  g_bufB);
    cudaGetSymbolAddress((void**)&pAh,   g_Ah);
    cudaGetSymbolAddress((void**)&pAl,   g_Al);
    cudaGetSymbolAddress((void**)&pBh,   g_Bh);
    cudaGetSymbolAddress((void**)&pBl,   g_Bl);
    cudaGetSymbolAddress((void**)&pg,    g_g);
    cudaGetSymbolAddress((void**)&pt1,   g_t1);
    cudaGetSymbolAddress((void**)&pxc,   g_xc);
    cudaGetSymbolAddress((void**)&pxt2c, g_xt2c);
    cudaGetSymbolAddress((void**)&pxt1c, g_xt1c);
    cudaGetSymbolAddress((void**)&pf1,   g_f1);
    cudaGetSymbolAddress((void**)&pf2,   g_f2);

    // 0) init accumulators
    k_init<<<(NN * NH + 255) / 256, 256>>>();

    // 1) h = x @ W_gat  via split-bf16 tensor cores  [50000,78]@[78,780]
    {
        size_t na = (size_t)NN * KP1;
        k_convA<false><<<(int)((na + 255) / 256), 256>>>(x, NN, FD, KP1, pAh, pAl);
        size_t nb = (size_t)KP1 * CC;
        k_convB<<<(int)((nb + 255) / 256), 256>>>(W_gat, FD, CC, KP1, pBh, pBl);
        wmma_gemm<<<wmma_grid(NN, CC), 256>>>(pAh, pAl, pBh, pBl, bufA, NN, CC, KP1, CC);
    }

    // 2) attention logits per node/head
    k_compute_a<<<(NN * NH + 255) / 256, 256>>>(att_src, att_dst);

    // 3) edge e + segment max + deg
    k_edge_e<<<(E + 255) / 256, 256>>>(ei, E0, E);

    // 4) exp + segment sum
    k_edge_softmax<<<(E + 255) / 256, 256>>>(ei, E0, E);

    // 5) gat_out = bias, then scatter-add messages
    k_fill_bias_B<<<(NN * CC + 255) / 256, 256>>>(b_gat);
    k_gat_agg<<<E, 256>>>(ei, E0);

    // 6) dinv + graph node counts
    k_node_dinv_cnt<<<(NN + 255) / 256, 256>>>(batch);

    // 7) hg = relu(gat_out) @ W_gcn  via split-bf16 tensor cores  [50000,780]@[780,780]
    {
        size_t na = (size_t)NN * KP2;
        k_convA<true><<<(int)((na + 255) / 256), 256>>>(bufB, NN, CC, KP2, pAh, pAl);
        size_t nb = (size_t)KP2 * CC;
        k_convB<<<(int)((nb + 255) / 256), 256>>>(W_gcn, CC, CC, KP2, pBh, pBl);
        wmma_gemm<<<wmma_grid(NN, CC), 256>>>(pAh, pAl, pBh, pBl, bufA, NN, CC, KP2, CC);
    }

    // 8) gcn_out = bias, scatter-add normalized messages
    k_fill_bias_B<<<(NN * CC + 255) / 256, 256>>>(b_gcn);
    k_gcn_agg<<<E, 256>>>(ei, E0);

    // 9) relu + global max/mean pool
    k_pool<<<(NN * CC + 255) / 256, 256>>>(batch);
    k_pool_fin<<<(NB * CC + 255) / 256, 256>>>();

    // 10) graph MLP head (small M — fp32 sgemm fine)
    sgemm_kernel<true ><<<gemm_grid(NB, 1500), 256>>>(pg,  W_fcg1, b_fcg1, pt1, NB, 1500, 1560, 1500);
    sgemm_kernel<false><<<gemm_grid(NB, 128),  256>>>(pt1, W_fcg2, b_fcg2, pxc + 0,   NB, 128, 1500, 384);

    // 11) protein branches
    k_conv2<<<NB, 256>>>(target2, emb, Wc2, bc2);
    sgemm_kernel<false><<<gemm_grid(NB, 128),  256>>>(pxt2c, W_fc2xt, b_fc2xt, pxc + 256, NB, 128, 3872, 384);
    k_conv1<<<NB, 544>>>(target1, Wc1, bc1);
    sgemm_kernel<false><<<gemm_grid(NB, 128),  256>>>(pxt1c, W_fc1xt, b_fc1xt, pxc + 128, NB, 128, 544, 384);

    // 12) final MLP
    sgemm_kernel<true ><<<gemm_grid(NB, 1024), 256>>>(pxc, W_fc1, b_fc1, pf1, NB, 1024, 384, 1024);
    sgemm_kernel<true ><<<gemm_grid(NB, 512),  256>>>(pf1, W_fc2, b_fc2, pf2, NB, 512, 1024, 512);
    sgemm_kernel<false><<<gemm_grid(NB, 1),    256>>>(pf2, W_out, b_out, out, NB, 1, 512, 1);
}

// round 3
// speedup vs baseline: 1.4216x; 1.2868x over previous
#include <cuda_runtime.h>
#include <cuda_bf16.h>
#include <mma.h>
#include <math.h>

using namespace nvcuda;

// ---------------- problem constants ----------------
#define NN 50000      // nodes
#define NB 128        // graphs / batch
#define NH 10         // heads
#define FD 78         // per-head feature
#define CC 780        // NH*FD
#define E0MAX 150000
#define EMAX  (E0MAX + NN)   // edges incl self loops
#define KP2 784              // 780 padded to mult of 16
#define KP1 80               // 78 padded to mult of 16

// ---------------- scratch (device globals; no allocs) ----------------
__device__ float g_bufA[NN * CC];   // h = x@W_gat, later hg = relu(gat)@W_gcn
__device__ float g_bufB[NN * CC];   // gat_out, later gcn_out
__device__ __nv_bfloat16 g_Ah[NN * KP2];
__device__ __nv_bfloat16 g_Al[NN * KP2];
__device__ __nv_bfloat16 g_Bh[KP2 * CC];
__device__ __nv_bfloat16 g_Bl[KP2 * CC];
__device__ float g_as[NN * NH];
__device__ float g_ad[NN * NH];
__device__ int   g_degi[NN];
__device__ int   g_off[NN + 1];
__device__ int   g_cur[NN];
__device__ int   g_srccsr[EMAX];
__device__ float g_dinv[NN];
__device__ int   g_bstart[NB + 1];
__device__ float g_g[NB * 1560];
__device__ float g_t1[NB * 1500];
__device__ float g_xc[NB * 384];
__device__ float g_xt2c[NB * 3872];
__device__ float g_xt1c[NB * 544];
__device__ float g_f1[NB * 1024];
__device__ float g_f2[NB * 512];

// ---------------- helpers ----------------
__device__ __forceinline__ void edge_sd(const int* ei, int E0, int e, int& s, int& d) {
    if (e < E0) { s = ei[e]; d = ei[E0 + e]; }
    else        { s = e - E0; d = e - E0; }
}

// ---------------- CSR build ----------------
__global__ void k_zero_deg() {
    int i = blockIdx.x * blockDim.x + threadIdx.x;
    if (i < NN) g_degi[i] = 0;
}

__global__ void k_count(const int* __restrict__ ei, int E0, int E) {
    int e = blockIdx.x * blockDim.x + threadIdx.x;
    if (e >= E) return;
    int s, d; edge_sd(ei, E0, e, s, d);
    (void)s;
    atomicAdd(&g_degi[d], 1);
}

__global__ void k_scan() {
    __shared__ int sh[1024];
    __shared__ int carry_s;
    int tid = threadIdx.x;
    if (tid == 0) carry_s = 0;
    __syncthreads();
    for (int base = 0; base < NN; base += 1024) {
        int i = base + tid;
        int v = (i < NN) ? g_degi[i] : 0;
        sh[tid] = v;
        __syncthreads();
        #pragma unroll
        for (int ofs = 1; ofs < 1024; ofs <<= 1) {
            int t = (tid >= ofs) ? sh[tid - ofs] : 0;
            __syncthreads();
            sh[tid] += t;
            __syncthreads();
        }
        int incl = sh[tid];
        if (i < NN) g_off[i] = carry_s + incl - v;
        __syncthreads();
        if (tid == 1023) carry_s += incl;
        __syncthreads();
    }
    if (tid == 0) g_off[NN] = carry_s;
}

__global__ void k_prep() {
    int n = blockIdx.x * blockDim.x + threadIdx.x;
    if (n >= NN) return;
    g_cur[n] = g_off[n];
    float dg = (float)g_degi[n];
    g_dinv[n] = (dg > 0.f) ? rsqrtf(dg) : 0.f;
}

__global__ void k_fillcsr(const int* __restrict__ ei, int E0, int E) {
    int e = blockIdx.x * blockDim.x + threadIdx.x;
    if (e >= E) return;
    int s, d; edge_sd(ei, E0, e, s, d);
    int pos = atomicAdd(&g_cur[d], 1);
    g_srccsr[pos] = s;
}

__global__ void k_bstart(const int* __restrict__ batch) {
    int n = blockIdx.x * blockDim.x + threadIdx.x;
    if (n >= NN) return;
    int bn = batch[n];
    int bp = (n == 0) ? -1 : batch[n - 1];
    for (int g = bp + 1; g <= bn; g++) g_bstart[g] = n;
    if (n == NN - 1)
        for (int g = bn + 1; g <= NB; g++) g_bstart[g] = NN;
}

// ---------------- split-bf16 conversion kernels ----------------
template<bool RELU>
__global__ void k_convA(const float* __restrict__ src, int M, int K, int Kp,
                        __nv_bfloat16* __restrict__ Ah, __nv_bfloat16* __restrict__ Al)
{
    size_t idx = (size_t)blockIdx.x * blockDim.x + threadIdx.x;
    if (idx >= (size_t)M * Kp) return;
    int c = (int)(idx % Kp);
    int r = (int)(idx / Kp);
    float v = 0.f;
    if (c < K) {
        v = src[(size_t)r * K + c];
        if (RELU) v = fmaxf(v, 0.f);
    }
    __nv_bfloat16 h = __float2bfloat16(v);
    Ah[idx] = h;
    Al[idx] = __float2bfloat16(v - __bfloat162float(h));
}

__global__ void k_convB(const float* __restrict__ W, int K, int N, int Kp,
                        __nv_bfloat16* __restrict__ Bh, __nv_bfloat16* __restrict__ Bl)
{
    size_t idx = (size_t)blockIdx.x * blockDim.x + threadIdx.x;
    if (idx >= (size_t)Kp * N) return;
    int n = (int)(idx % N);
    int k = (int)(idx / N);
    float v = (k < K) ? W[(size_t)k * N + n] : 0.f;
    __nv_bfloat16 h = __float2bfloat16(v);
    Bh[idx] = h;
    Bl[idx] = __float2bfloat16(v - __bfloat162float(h));
}

// ---------------- split-bf16 wmma GEMM ----------------
__global__ __launch_bounds__(256)
void wmma_gemm(const __nv_bfloat16* __restrict__ Ah, const __nv_bfloat16* __restrict__ Al,
               const __nv_bfloat16* __restrict__ Bh, const __nv_bfloat16* __restrict__ Bl,
               float* __restrict__ C, int M, int N, int Kp, int ldc)
{
    __shared__ __align__(16) __nv_bfloat16 AsH[128][16];
    __shared__ __align__(16) __nv_bfloat16 AsL[128][16];
    __shared__ __align__(16) __nv_bfloat16 BsH[16][128];
    __shared__ __align__(16) __nv_bfloat16 BsL[16][128];
    __shared__ __align__(16) float stage[8][16][16];

    int tid = threadIdx.x;
    int wid = tid >> 5, lane = tid & 31;
    int wm = wid & 3, wn = wid >> 2;
    int brow = blockIdx.y * 128, bcol = blockIdx.x * 128;

    wmma::fragment<wmma::accumulator, 16, 16, 16, float> acc[2][4];
    #pragma unroll
    for (int i = 0; i < 2; i++)
        #pragma unroll
        for (int j = 0; j < 4; j++) wmma::fill_fragment(acc[i][j], 0.f);

    const bool fullN = (bcol + 128 <= N);

    for (int k0 = 0; k0 < Kp; k0 += 16) {
        {
            int row = tid >> 1, seg = tid & 1;
            int gm = brow + row;
            uint4 vh = make_uint4(0, 0, 0, 0), vl = vh;
            if (gm < M) {
                const uint4* ph = (const uint4*)(Ah + (size_t)gm * Kp + k0);
                const uint4* pl = (const uint4*)(Al + (size_t)gm * Kp + k0);
                vh = ph[seg]; vl = pl[seg];
            }
            ((uint4*)&AsH[row][0])[seg] = vh;
            ((uint4*)&AsL[row][0])[seg] = vl;
        }
        if (fullN) {
            int k = tid >> 4, cs = tid & 15;
            size_t base = (size_t)(k0 + k) * N + bcol + cs * 8;
            const uint2* ph = (const uint2*)(Bh + base);
            const uint2* pl = (const uint2*)(Bl + base);
            uint2 h0 = ph[0], h1 = ph[1];
            uint2 l0 = pl[0], l1 = pl[1];
            uint2* dh = (uint2*)&BsH[k][cs * 8];
            uint2* dl = (uint2*)&BsL[k][cs * 8];
            dh[0] = h0; dh[1] = h1;
            dl[0] = l0; dl[1] = l1;
        } else {
            __nv_bfloat16 z = __float2bfloat16(0.f);
            for (int idx = tid; idx < 16 * 128; idx += 256) {
                int k = idx >> 7, c = idx & 127;
                int gn = bcol + c;
                __nv_bfloat16 vh = z, vl = z;
                if (gn < N) {
                    size_t o = (size_t)(k0 + k) * N + gn;
                    vh = Bh[o]; vl = Bl[o];
                }
                BsH[k][c] = vh; BsL[k][c] = vl;
            }
        }
        __syncthreads();

        wmma::fragment<wmma::matrix_a, 16, 16, 16, __nv_bfloat16, wmma::row_major> ah[2], al[2];
        wmma::fragment<wmma::matrix_b, 16, 16, 16, __nv_bfloat16, wmma::row_major> bh[4], bl[4];
        #pragma unroll
        for (int i = 0; i < 2; i++) {
            wmma::load_matrix_sync(ah[i], &AsH[wm * 32 + i * 16][0], 16);
            wmma::load_matrix_sync(al[i], &AsL[wm * 32 + i * 16][0], 16);
        }
        #pragma unroll
        for (int j = 0; j < 4; j++) {
            wmma::load_matrix_sync(bh[j], &BsH[0][wn * 64 + j * 16], 128);
            wmma::load_matrix_sync(bl[j], &BsL[0][wn * 64 + j * 16], 128);
        }
        #pragma unroll
        for (int i = 0; i < 2; i++)
            #pragma unroll
            for (int j = 0; j < 4; j++) {
                wmma::mma_sync(acc[i][j], ah[i], bh[j], acc[i][j]);
                wmma::mma_sync(acc[i][j], ah[i], bl[j], acc[i][j]);
                wmma::mma_sync(acc[i][j], al[i], bh[j], acc[i][j]);
            }
        __syncthreads();
    }

    #pragma unroll
    for (int i = 0; i < 2; i++)
        #pragma unroll
        for (int j = 0; j < 4; j++) {
            wmma::store_matrix_sync(&stage[wid][0][0], acc[i][j], 16, wmma::mem_row_major);
            __syncwarp();
            int gm0 = brow + wm * 32 + i * 16;
            int gn0 = bcol + wn * 64 + j * 16;
            for (int e = lane; e < 256; e += 32) {
                int r = e >> 4, c = e & 15;
                int gm = gm0 + r, gn = gn0 + c;
                if (gm < M && gn < N) C[(size_t)gm * ldc + gn] = stage[wid][r][c];
            }
            __syncwarp();
        }
}

// ---------------- fp32 tiled SGEMM for the small FC head ----------------
template<bool RELU_OUT>
__global__ void sgemm_kernel(const float* __restrict__ A, const float* __restrict__ B,
                             const float* __restrict__ bias, float* __restrict__ C,
                             int M, int N, int K, int ldc)
{
    const int BM = 64, BN = 64, BK = 16;
    __shared__ float As[BK][BM + 1];
    __shared__ float Bs[BK][BN + 1];
    int tid = threadIdx.x;
    int tx = tid & 15, ty = tid >> 4;
    int brow = blockIdx.y * BM;
    int bcol = blockIdx.x * BN;

    float acc[4][4];
    #pragma unroll
    for (int i = 0; i < 4; i++)
        #pragma unroll
        for (int j = 0; j < 4; j++) acc[i][j] = 0.f;

    for (int k0 = 0; k0 < K; k0 += BK) {
        #pragma unroll
        for (int i = 0; i < 4; i++) {
            int idx = tid + i * 256;
            int m = idx >> 4, k = idx & 15;
            int gm = brow + m, gk = k0 + k;
            As[k][m] = (gm < M && gk < K) ? A[(size_t)gm * K + gk] : 0.f;
        }
        #pragma unroll
        for (int i = 0; i < 4; i++) {
            int idx = tid + i * 256;
            int k = idx >> 6, n = idx & 63;
            int gk = k0 + k, gn = bcol + n;
            Bs[k][n] = (gk < K && gn < N) ? B[(size_t)gk * N + gn] : 0.f;
        }
        __syncthreads();
        #pragma unroll
        for (int kk = 0; kk < BK; kk++) {
            float a[4], b[4];
            #pragma unroll
            for (int i = 0; i < 4; i++) a[i] = As[kk][ty * 4 + i];
            #pragma unroll
            for (int j = 0; j < 4; j++) b[j] = Bs[kk][tx * 4 + j];
            #pragma unroll
            for (int i = 0; i < 4; i++)
                #pragma unroll
                for (int j = 0; j < 4; j++) acc[i][j] += a[i] * b[j];
        }
        __syncthreads();
    }
    #pragma unroll
    for (int i = 0; i < 4; i++) {
        int gm = brow + ty * 4 + i;
        if (gm >= M) continue;
        #pragma unroll
        for (int j = 0; j < 4; j++) {
            int gn = bcol + tx * 4 + j;
            if (gn >= N) continue;
            float v = acc[i][j] + (bias ? bias[gn] : 0.f);
            if (RELU_OUT) v = fmaxf(v, 0.f);
            C[(size_t)gm * ldc + gn] = v;
        }
    }
}

// ---------------- attention logits per node/head ----------------
__global__ void k_compute_a(const float* __restrict__ att_src, const float* __restrict__ att_dst) {
    int i = blockIdx.x * blockDim.x + threadIdx.x;
    if (i >= NN * NH) return;
    int n = i / NH, h = i % NH;
    const float* hp = &g_bufA[(size_t)n * CC + h * FD];
    const float* ws = &att_src[h * FD];
    const float* wd = &att_dst[h * FD];
    float s = 0.f, d = 0.f;
    #pragma unroll 6
    for (int f = 0; f < FD; f++) { float v = hp[f]; s += v * ws[f]; d += v * wd[f]; }
    g_as[i] = s;
    g_ad[i] = d;
}

// ---------------- fused GAT gather: one warp per dst node ----------------
__global__ __launch_bounds__(256)
void k_gat_gather(const float* __restrict__ bias) {
    int w = (blockIdx.x * blockDim.x + threadIdx.x) >> 5;
    if (w >= NN) return;
    int lane = threadIdx.x & 31;
    int beg = g_off[w], end = g_off[w + 1];

    float ad = (lane < NH) ? g_ad[w * NH + lane] : 0.f;

    // pass 1: online softmax (lanes 0..NH-1 own one head each)
    float m = -1e30f, ssum = 0.f;
    for (int j = beg; j < end; j++) {
        int s = g_srccsr[j];
        if (lane < NH) {
            float e = g_as[s * NH + lane] + ad;
            e = (e > 0.f) ? e : 0.2f * e;
            float mn = fmaxf(m, e);
            ssum = ssum * expf(m - mn) + expf(e - mn);
            m = mn;
        }
    }
    float inv = 1.f / (ssum + 1e-16f);

    // pass 2: weighted accumulation; lane owns f = lane + 32*i
    float acc[25];
    #pragma unroll
    for (int i = 0; i < 25; i++) acc[i] = 0.f;

    for (int j = beg; j < end; j++) {
        int s = g_srccsr[j];
        float alpha = 0.f;
        if (lane < NH) {
            float e = g_as[s * NH + lane] + ad;
            e = (e > 0.f) ? e : 0.2f * e;
            alpha = expf(e - m) * inv;
        }
        const float* row = g_bufA + (size_t)s * CC;
        #pragma unroll
        for (int i = 0; i < 25; i++) {
            int f = lane + (i << 5);
            int h = (f < CC ? f : CC - 1) / FD;
            float al = __shfl_sync(0xffffffffu, alpha, h);
            if (f < CC) acc[i] += row[f] * al;
        }
    }
    #pragma unroll
    for (int i = 0; i < 25; i++) {
        int f = lane + (i << 5);
        if (f < CC) g_bufB[(size_t)w * CC + f] = acc[i] + bias[f];
    }
}

// ---------------- fused GCN gather: one warp per dst node ----------------
__global__ __launch_bounds__(256)
void k_gcn_gather(const float* __restrict__ bias) {
    int w = (blockIdx.x * blockDim.x + threadIdx.x) >> 5;
    if (w >= NN) return;
    int lane = threadIdx.x & 31;
    int beg = g_off[w], end = g_off[w + 1];
    float dv = g_dinv[w];

    float acc[25];
    #pragma unroll
    for (int i = 0; i < 25; i++) acc[i] = 0.f;

    for (int j = beg; j < end; j++) {
        int s = g_srccsr[j];
        float nr = g_dinv[s] * dv;
        const float* row = g_bufA + (size_t)s * CC;
        #pragma unroll
        for (int i = 0; i < 25; i++) {
            int f = lane + (i << 5);
            if (f < CC) acc[i] += row[f] * nr;
        }
    }
    #pragma unroll
    for (int i = 0; i < 25; i++) {
        int f = lane + (i << 5);
        if (f < CC) g_bufB[(size_t)w * CC + f] = acc[i] + bias[f];
    }
}

// ---------------- pooling (batch sorted -> contiguous ranges) ----------------
__global__ void k_pool2() {
    int b = blockIdx.y;
    int f = blockIdx.x * 256 + threadIdx.x;
    if (f >= CC) return;
    int s = g_bstart[b], e = g_bstart[b + 1];
    float mx = 0.f, sm = 0.f;
    for (int n = s; n < e; n++) {
        float v = fmaxf(g_bufB[(size_t)n * CC + f], 0.f);   // relu(gcn_out)
        mx = fmaxf(mx, v);
        sm += v;
    }
    g_g[b * 1560 + f] = mx;
    g_g[b * 1560 + 780 + f] = sm / fmaxf((float)(e - s), 1.f);
}

// ---------------- protein branches ----------------
__global__ void k_conv2(const int* __restrict__ t2, const float* __restrict__ emb,
                        const float* __restrict__ Wc2, const float* __restrict__ bc2)
{
    __shared__ float wag[26 * 256];
    int b = blockIdx.x;
    int tid = threadIdx.x;
    for (int v = 0; v < 26; v++) wag[v * 256 + tid] = 0.f;
    __syncthreads();
    int o = tid >> 3, k = tid & 7;
    const float* wcol = &Wc2[o * 8000 + k];
    const int* t2b = &t2[b * 1000];
    for (int i = 0; i < 1000; i++) {
        int v = t2b[i];
        wag[v * 256 + tid] += wcol[i * 8];
    }
    __syncthreads();
    for (int j = tid; j < 32 * 121; j += 256) {
        int oo = j / 121, l = j % 121;
        float acc = bc2[oo];
        for (int v = 0; v < 26; v++) {
            const float* wa = &wag[v * 256 + oo * 8];
            const float* er = &emb[v * 128 + l];
            #pragma unroll
            for (int kk = 0; kk < 8; kk++) acc += wa[kk] * er[kk];
        }
        g_xt2c[b * 3872 + j] = acc;
    }
}

__global__ void k_conv1(const float* __restrict__ t1, const float* __restrict__ Wc1,
                        const float* __restrict__ bc1)
{
    int b = blockIdx.x;
    int tid = threadIdx.x;
    int o = tid / 17, l = tid % 17;
    float acc = bc1[o];
    for (int i = 0; i < 20; i++) {
        const float* xr = &t1[b * 480 + i * 24 + l];
        const float* wr = &Wc1[o * 160 + i * 8];
        #pragma unroll
        for (int k = 0; k < 8; k++) acc += xr[k] * wr[k];
    }
    g_xt1c[b * 544 + tid] = acc;
}

// ---------------- launch ----------------
static inline dim3 gemm_grid(int M, int N) {
    return dim3((N + 63) / 64, (M + 63) / 64);
}
static inline dim3 wmma_grid(int M, int N) {
    return dim3((N + 127) / 128, (M + 127) / 128);
}

extern "C" void kernel_launch(void* const* d_in, const int* in_sizes, int n_in,
                              void* d_out, int out_size)
{
    const float* x       = (const float*)d_in[0];
    const int*   ei      = (const int*)  d_in[1];
    const int*   batch   = (const int*)  d_in[2];
    const float* target1 = (const float*)d_in[3];
    const int*   target2 = (const int*)  d_in[4];
    const float* W_gat   = (const float*)d_in[5];
    const float* att_src = (const float*)d_in[6];
    const float* att_dst = (const float*)d_in[7];
    const float* b_gat   = (const float*)d_in[8];
    const float* W_gcn   = (const float*)d_in[9];
    const float* b_gcn   = (const float*)d_in[10];
    const float* W_fcg1  = (const float*)d_in[11];
    const float* b_fcg1  = (const float*)d_in[12];
    const float* W_fcg2  = (const float*)d_in[13];
    const float* b_fcg2  = (const float*)d_in[14];
    const float* emb     = (const float*)d_in[15];
    const float* Wc2     = (const float*)d_in[16];
    const float* bc2     = (const float*)d_in[17];
    const float* W_fc2xt = (const float*)d_in[18];
    const float* b_fc2xt = (const float*)d_in[19];
    const float* Wc1     = (const float*)d_in[20];
    const float* bc1     = (const float*)d_in[21];
    const float* W_fc1xt = (const float*)d_in[22];
    const float* b_fc1xt = (const float*)d_in[23];
    const float* W_fc1   = (const float*)d_in[24];
    const float* b_fc1   = (const float*)d_in[25];
    const float* W_fc2   = (const float*)d_in[26];
    const float* b_fc2   = (const float*)d_in[27];
    const float* W_out   = (const float*)d_in[28];
    const float* b_out   = (const float*)d_in[29];
    float* out = (float*)d_out;

    int E0 = in_sizes[1] / 2;           // 150000
    int E  = E0 + NN;                   // + self loops

    float *bufA, *bufB, *pg, *pt1, *pxc, *pxt2c, *pxt1c, *pf1, *pf2;
    __nv_bfloat16 *pAh, *pAl, *pBh, *pBl;
    cudaGetSymbolAddress((void**)&bufA,  g_bufA);
    cudaGetSymbolAddress((void**)&bufB,  g_bufB);
    cudaGetSymbolAddress((void**)&pAh,   g_Ah);
    cudaGetSymbolAddress((void**)&pAl,   g_Al);
    cudaGetSymbolAddress((void**)&pBh,   g_Bh);
    cudaGetSymbolAddress((void**)&pBl,   g_Bl);
    cudaGetSymbolAddress((void**)&pg,    g_g);
    cudaGetSymbolAddress((void**)&pt1,   g_t1);
    cudaGetSymbolAddress((void**)&pxc,   g_xc);
    cudaGetSymbolAddress((void**)&pxt2c, g_xt2c);
    cudaGetSymbolAddress((void**)&pxt1c, g_xt1c);
    cudaGetSymbolAddress((void**)&pf1,   g_f1);
    cudaGetSymbolAddress((void**)&pf2,   g_f2);

    // --- CSR + batch boundaries ---
    k_zero_deg<<<(NN + 255) / 256, 256>>>();
    k_count<<<(E + 255) / 256, 256>>>(ei, E0, E);
    k_scan<<<1, 1024>>>();
    k_prep<<<(NN + 255) / 256, 256>>>();
    k_fillcsr<<<(E + 255) / 256, 256>>>(ei, E0, E);
    k_bstart<<<(NN + 255) / 256, 256>>>(batch);

    // --- h = x @ W_gat (split-bf16 tensor cores) ---
    {
        size_t na = (size_t)NN * KP1;
        k_convA<false><<<(int)((na + 255) / 256), 256>>>(x, NN, FD, KP1, pAh, pAl);
        size_t nb = (size_t)KP1 * CC;
        k_convB<<<(int)((nb + 255) / 256), 256>>>(W_gat, FD, CC, KP1, pBh, pBl);
        wmma_gemm<<<wmma_grid(NN, CC), 256>>>(pAh, pAl, pBh, pBl, bufA, NN, CC, KP1, CC);
    }

    // --- GAT: logits + fused softmax/aggregate gather ---
    k_compute_a<<<(NN * NH + 255) / 256, 256>>>(att_src, att_dst);
    k_gat_gather<<<(NN * 32 + 255) / 256, 256>>>(b_gat);

    // --- hg = relu(gat_out) @ W_gcn (split-bf16 tensor cores) ---
    {
        size_t na = (size_t)NN * KP2;
        k_convA<true><<<(int)((na + 255) / 256), 256>>>(bufB, NN, CC, KP2, pAh, pAl);
        size_t nb = (size_t)KP2 * CC;
        k_convB<<<(int)((nb + 255) / 256), 256>>>(W_gcn, CC, CC, KP2, pBh, pBl);
        wmma_gemm<<<wmma_grid(NN, CC), 256>>>(pAh, pAl, pBh, pBl, bufA, NN, CC, KP2, CC);
    }

    // --- GCN gather ---
    k_gcn_gather<<<(NN * 32 + 255) / 256, 256>>>(b_gcn);

    // --- pooling (no atomics; batch sorted) ---
    k_pool2<<<dim3(4, NB), 256>>>();

    // --- graph MLP head ---
    sgemm_kernel<true ><<<gemm_grid(NB, 1500), 256>>>(pg,  W_fcg1, b_fcg1, pt1, NB, 1500, 1560, 1500);
    sgemm_kernel<false><<<gemm_grid(NB, 128),  256>>>(pt1, W_fcg2, b_fcg2, pxc + 0,   NB, 128, 1500, 384);

    // --- protein branches ---
    k_conv2<<<NB, 256>>>(target2, emb, Wc2, bc2);
    sgemm_kernel<false><<<gemm_grid(NB, 128),  256>>>(pxt2c, W_fc2xt, b_fc2xt, pxc + 256, NB, 128, 3872, 384);
    k_conv1<<<NB, 544>>>(target1, Wc1, bc1);
    sgemm_kernel<false><<<gemm_grid(NB, 128),  256>>>(pxt1c, W_fc1xt, b_fc1xt, pxc + 128, NB, 128, 544, 384);

    // --- final MLP ---
    sgemm_kernel<true ><<<gemm_grid(NB, 1024), 256>>>(pxc, W_fc1, b_fc1, pf1, NB, 1024, 384, 1024);
    sgemm_kernel<true ><<<gemm_grid(NB, 512),  256>>>(pf1, W_fc2, b_fc2, pf2, NB, 512, 1024, 512);
    sgemm_kernel<false><<<gemm_grid(NB, 1),    256>>>(pf2, W_out, b_out, out, NB, 1, 512, 1);
}

// round 5
// speedup vs baseline: 2.1119x; 1.4856x over previous
#include <cuda_runtime.h>
#include <cuda_bf16.h>
#include <mma.h>
#include <math.h>
#include <cstdint>

using namespace nvcuda;

// ---------------- problem constants ----------------
#define NN 50000      // nodes
#define NB 128        // graphs / batch
#define NH 10         // heads
#define FD 78         // per-head feature
#define CC 780        // NH*FD
#define E0MAX 150000
#define EMAX  (E0MAX + NN)   // edges incl self loops
#define KP2 784              // 780 padded to mult of 16
#define KP1 80               // 78 padded to mult of 16
#define NP  896              // N padded to grid coverage (7*128) for B
#define NBLK 49              // ceil(NN/1024)

// ---------------- scratch (device globals; no allocs) ----------------
__device__ float g_bufA[NN * CC];   // h = x@W_gat, later hg = relu(gat)@W_gcn
__device__ float g_bufB[NN * CC];   // gcn_out
__device__ __nv_bfloat16 g_Ah[NN * KP2];
__device__ __nv_bfloat16 g_Al[NN * KP2];
__device__ __nv_bfloat16 g_Bh[KP2 * NP];
__device__ __nv_bfloat16 g_Bl[KP2 * NP];
__device__ float g_as[NN * NH];
__device__ float g_ad[NN * NH];
__device__ int   g_degi[NN];
__device__ int   g_off[NN + 1];
__device__ int   g_cur[NN];
__device__ int   g_srccsr[EMAX];
__device__ float g_dinv[NN];
__device__ int   g_bstart[NB + 1];
__device__ int   g_bsum[64];
__device__ int   g_bsum2[64];
__device__ float g_g[NB * 1560];
__device__ float g_t1[NB * 1500];
__device__ float g_xc[NB * 384];
__device__ float g_xt2c[NB * 3872];
__device__ float g_xt1c[NB * 544];
__device__ float g_f1[NB * 1024];
__device__ float g_f2[NB * 512];

// ---------------- helpers ----------------
__device__ __forceinline__ void edge_sd(const int* ei, int E0, int e, int& s, int& d) {
    if (e < E0) { s = ei[e]; d = ei[E0 + e]; }
    else        { s = e - E0; d = e - E0; }
}

__device__ __forceinline__ void cp_async16(unsigned int smem, const void* gmem, int srcbytes) {
    asm volatile("cp.async.cg.shared.global [%0], [%1], 16, %2;\n"
                 :: "r"(smem), "l"(gmem), "r"(srcbytes));
}
__device__ __forceinline__ unsigned int smem_u32(const void* p) {
    return (unsigned int)__cvta_generic_to_shared(p);
}

// ---------------- CSR build ----------------
__global__ void k_zero_deg() {
    int i = blockIdx.x * blockDim.x + threadIdx.x;
    if (i < NN) g_degi[i] = 0;
}

__global__ void k_count(const int* __restrict__ ei, int E0, int E) {
    int e = blockIdx.x * blockDim.x + threadIdx.x;
    if (e >= E) return;
    int s, d; edge_sd(ei, E0, e, s, d);
    (void)s;
    atomicAdd(&g_degi[d], 1);
}

__global__ void k_scan1() {
    __shared__ int sh[1024];
    int tid = threadIdx.x;
    int i = blockIdx.x * 1024 + tid;
    int v = (i < NN) ? g_degi[i] : 0;
    sh[tid] = v;
    __syncthreads();
    #pragma unroll
    for (int o = 1; o < 1024; o <<= 1) {
        int t = (tid >= o) ? sh[tid - o] : 0;
        __syncthreads();
        sh[tid] += t;
        __syncthreads();
    }
    if (i < NN) g_off[i] = sh[tid] - v;      // block-local exclusive
    if (tid == 1023) g_bsum[blockIdx.x] = sh[1023];
}

__global__ void k_scan2() {
    __shared__ int sh[64];
    int t = threadIdx.x;
    int v = (t < NBLK) ? g_bsum[t] : 0;
    sh[t] = v;
    __syncthreads();
    #pragma unroll
    for (int o = 1; o < 64; o <<= 1) {
        int x = (t >= o) ? sh[t - o] : 0;
        __syncthreads();
        sh[t] += x;
        __syncthreads();
    }
    if (t < NBLK) g_bsum2[t] = sh[t] - v;    // exclusive
    if (t == 63) g_off[NN] = sh[63];         // total
}

__global__ void k_scan3() {
    int i = blockIdx.x * blockDim.x + threadIdx.x;
    if (i < NN) g_off[i] += g_bsum2[i >> 10];
}

__global__ void k_prep() {
    int n = blockIdx.x * blockDim.x + threadIdx.x;
    if (n >= NN) return;
    g_cur[n] = g_off[n];
    float dg = (float)g_degi[n];
    g_dinv[n] = (dg > 0.f) ? rsqrtf(dg) : 0.f;
}

__global__ void k_fillcsr(const int* __restrict__ ei, int E0, int E) {
    int e = blockIdx.x * blockDim.x + threadIdx.x;
    if (e >= E) return;
    int s, d; edge_sd(ei, E0, e, s, d);
    int pos = atomicAdd(&g_cur[d], 1);
    g_srccsr[pos] = s;
}

__global__ void k_bstart(const int* __restrict__ batch) {
    int n = blockIdx.x * blockDim.x + threadIdx.x;
    if (n >= NN) return;
    int bn = batch[n];
    int bp = (n == 0) ? -1 : batch[n - 1];
    for (int g = bp + 1; g <= bn; g++) g_bstart[g] = n;
    if (n == NN - 1)
        for (int g = bn + 1; g <= NB; g++) g_bstart[g] = NN;
}

// ---------------- split-bf16 conversion ----------------
template<bool RELU>
__global__ void k_convA(const float* __restrict__ src, int M, int K, int Kp,
                        __nv_bfloat16* __restrict__ Ah, __nv_bfloat16* __restrict__ Al)
{
    size_t idx = (size_t)blockIdx.x * blockDim.x + threadIdx.x;
    if (idx >= (size_t)M * Kp) return;
    int c = (int)(idx % Kp);
    int r = (int)(idx / Kp);
    float v = 0.f;
    if (c < K) {
        v = src[(size_t)r * K + c];
        if (RELU) v = fmaxf(v, 0.f);
    }
    __nv_bfloat16 h = __float2bfloat16(v);
    Ah[idx] = h;
    Al[idx] = __float2bfloat16(v - __bfloat162float(h));
}

__global__ void k_convB(const float* __restrict__ W, int K, int N, int Kp,
                        __nv_bfloat16* __restrict__ Bh, __nv_bfloat16* __restrict__ Bl)
{
    size_t idx = (size_t)blockIdx.x * blockDim.x + threadIdx.x;
    if (idx >= (size_t)Kp * NP) return;
    int n = (int)(idx % NP);
    int k = (int)(idx / NP);
    float v = (k < K && n < N) ? W[(size_t)k * N + n] : 0.f;
    __nv_bfloat16 h = __float2bfloat16(v);
    Bh[idx] = h;
    Bl[idx] = __float2bfloat16(v - __bfloat162float(h));
}

// ---------------- split-bf16 wmma GEMM v2 ----------------
// A: [M, Kp] hi/lo row-major.  B: [Kp, NP] hi/lo row-major (zero-padded cols).
// C: fp32 [M, ldc].  Block tile 128x128, 8 warps (4M x 2N), warp tile 32x64.
// Double-buffered cp.async, conflict-free padded smem, direct-store epilogue.
#define ALD 24     // A smem row stride (elements): 48B rows
#define BLD 136    // B smem row stride: 272B rows
__global__ __launch_bounds__(256)
void wmma_gemm(const __nv_bfloat16* __restrict__ Ah, const __nv_bfloat16* __restrict__ Al,
               const __nv_bfloat16* __restrict__ Bh, const __nv_bfloat16* __restrict__ Bl,
               float* __restrict__ C, int M, int N, int Kp, int ldc)
{
    __shared__ __align__(16) __nv_bfloat16 AsH[2][128][ALD];
    __shared__ __align__(16) __nv_bfloat16 AsL[2][128][ALD];
    __shared__ __align__(16) __nv_bfloat16 BsH[2][16][BLD];
    __shared__ __align__(16) __nv_bfloat16 BsL[2][16][BLD];

    int tid = threadIdx.x;
    int wid = tid >> 5, lane = tid & 31;
    int wm = wid & 3, wn = wid >> 2;
    int brow = blockIdx.y * 128, bcol = blockIdx.x * 128;
    int ns = Kp >> 4;

    wmma::fragment<wmma::accumulator, 16, 16, 16, float> acc[2][4];
    #pragma unroll
    for (int i = 0; i < 2; i++)
        #pragma unroll
        for (int j = 0; j < 4; j++) wmma::fill_fragment(acc[i][j], 0.f);

    // ---- slab loader (one commit group per call) ----
    auto load_slab = [&](int k0, int buf) {
        // A: 128 rows x 16 cols hi+lo = 512 x 16B chunks
        #pragma unroll
        for (int q = 0; q < 2; q++) {
            int a = (tid << 1) | q;               // 0..511
            int row = a >> 2, part = (a >> 1) & 1, seg = a & 1;
            int gm = brow + row;
            const __nv_bfloat16* srcb = part ? Al : Ah;
            const void* src = (gm < M) ? (const void*)(srcb + (size_t)gm * Kp + k0 + seg * 8)
                                       : (const void*)srcb;
            unsigned int dst = smem_u32(part ? &AsL[buf][row][seg * 8] : &AsH[buf][row][seg * 8]);
            cp_async16(dst, src, (gm < M) ? 16 : 0);
        }
        // B: 16 rows x 128 cols hi+lo = 512 x 16B chunks (always in-bounds: NP-padded)
        #pragma unroll
        for (int q = 0; q < 2; q++) {
            int b = (tid << 1) | q;
            int k = b >> 5, c = (b >> 1) & 15, part = b & 1;
            const __nv_bfloat16* srcb = part ? Bl : Bh;
            const void* src = srcb + (size_t)(k0 + k) * NP + bcol + c * 8;
            unsigned int dst = smem_u32(part ? &BsL[buf][k][c * 8] : &BsH[buf][k][c * 8]);
            cp_async16(dst, src, 16);
        }
        asm volatile("cp.async.commit_group;\n");
    };

    load_slab(0, 0);

    for (int it = 0; it < ns; it++) {
        int buf = it & 1;
        if (it + 1 < ns) {
            load_slab((it + 1) << 4, buf ^ 1);
            asm volatile("cp.async.wait_group 1;\n");
        } else {
            asm volatile("cp.async.wait_group 0;\n");
        }
        __syncthreads();

        wmma::fragment<wmma::matrix_a, 16, 16, 16, __nv_bfloat16, wmma::row_major> ah[2], al[2];
        #pragma unroll
        for (int i = 0; i < 2; i++) {
            wmma::load_matrix_sync(ah[i], &AsH[buf][wm * 32 + i * 16][0], ALD);
            wmma::load_matrix_sync(al[i], &AsL[buf][wm * 32 + i * 16][0], ALD);
        }
        #pragma unroll
        for (int j = 0; j < 4; j++) {
            wmma::fragment<wmma::matrix_b, 16, 16, 16, __nv_bfloat16, wmma::row_major> bh, bl;
            wmma::load_matrix_sync(bh, &BsH[buf][0][wn * 64 + j * 16], BLD);
            wmma::load_matrix_sync(bl, &BsL[buf][0][wn * 64 + j * 16], BLD);
            #pragma unroll
            for (int i = 0; i < 2; i++) {
                wmma::mma_sync(acc[i][j], ah[i], bh, acc[i][j]);
                wmma::mma_sync(acc[i][j], ah[i], bl, acc[i][j]);
                wmma::mma_sync(acc[i][j], al[i], bh, acc[i][j]);
            }
        }
        __syncthreads();
    }

    // ---- epilogue ----
    if (brow + 128 <= M && bcol + 128 <= N) {
        #pragma unroll
        for (int i = 0; i < 2; i++)
            #pragma unroll
            for (int j = 0; j < 4; j++) {
                int gm0 = brow + wm * 32 + i * 16;
                int gn0 = bcol + wn * 64 + j * 16;
                wmma::store_matrix_sync(&C[(size_t)gm0 * ldc + gn0], acc[i][j], ldc,
                                        wmma::mem_row_major);
            }
    } else {
        // boundary tile: stage through (reused) A smem
        float* stagep = (float*)&AsH[0][0][0] + wid * 272;
        __syncthreads();
        #pragma unroll
        for (int i = 0; i < 2; i++)
            #pragma unroll
            for (int j = 0; j < 4; j++) {
                wmma::store_matrix_sync(stagep, acc[i][j], 16, wmma::mem_row_major);
                __syncwarp();
                int gm0 = brow + wm * 32 + i * 16;
                int gn0 = bcol + wn * 64 + j * 16;
                for (int e = lane; e < 256; e += 32) {
                    int r = e >> 4, c = e & 15;
                    int gm = gm0 + r, gn = gn0 + c;
                    if (gm < M && gn < N) C[(size_t)gm * ldc + gn] = stagep[r * 16 + c];
                }
                __syncwarp();
            }
    }
}

// ---------------- fp32 tiled SGEMM for the small FC head ----------------
template<bool RELU_OUT>
__global__ void sgemm_kernel(const float* __restrict__ A, const float* __restrict__ B,
                             const float* __restrict__ bias, float* __restrict__ C,
                             int M, int N, int K, int ldc)
{
    const int BM = 64, BN = 64, BK = 16;
    __shared__ float As[BK][BM + 1];
    __shared__ float Bs[BK][BN + 1];
    int tid = threadIdx.x;
    int tx = tid & 15, ty = tid >> 4;
    int brow = blockIdx.y * BM;
    int bcol = blockIdx.x * BN;

    float acc[4][4];
    #pragma unroll
    for (int i = 0; i < 4; i++)
        #pragma unroll
        for (int j = 0; j < 4; j++) acc[i][j] = 0.f;

    for (int k0 = 0; k0 < K; k0 += BK) {
        #pragma unroll
        for (int i = 0; i < 4; i++) {
            int idx = tid + i * 256;
            int m = idx >> 4, k = idx & 15;
            int gm = brow + m, gk = k0 + k;
            As[k][m] = (gm < M && gk < K) ? A[(size_t)gm * K + gk] : 0.f;
        }
        #pragma unroll
        for (int i = 0; i < 4; i++) {
            int idx = tid + i * 256;
            int k = idx >> 6, n = idx & 63;
            int gk = k0 + k, gn = bcol + n;
            Bs[k][n] = (gk < K && gn < N) ? B[(size_t)gk * N + gn] : 0.f;
        }
        __syncthreads();
        #pragma unroll
        for (int kk = 0; kk < BK; kk++) {
            float a[4], b[4];
            #pragma unroll
            for (int i = 0; i < 4; i++) a[i] = As[kk][ty * 4 + i];
            #pragma unroll
            for (int j = 0; j < 4; j++) b[j] = Bs[kk][tx * 4 + j];
            #pragma unroll
            for (int i = 0; i < 4; i++)
                #pragma unroll
                for (int j = 0; j < 4; j++) acc[i][j] += a[i] * b[j];
        }
        __syncthreads();
    }
    #pragma unroll
    for (int i = 0; i < 4; i++) {
        int gm = brow + ty * 4 + i;
        if (gm >= M) continue;
        #pragma unroll
        for (int j = 0; j < 4; j++) {
            int gn = bcol + tx * 4 + j;
            if (gn >= N) continue;
            float v = acc[i][j] + (bias ? bias[gn] : 0.f);
            if (RELU_OUT) v = fmaxf(v, 0.f);
            C[(size_t)gm * ldc + gn] = v;
        }
    }
}

// ---------------- attention logits: warp per node, coalesced ----------------
__global__ __launch_bounds__(256)
void k_compute_a(const float* __restrict__ att_src, const float* __restrict__ att_dst) {
    __shared__ float ws[CC], wd[CC];
    for (int i = threadIdx.x; i < CC; i += 256) { ws[i] = att_src[i]; wd[i] = att_dst[i]; }
    __syncthreads();
    int warp = threadIdx.x >> 5, lane = threadIdx.x & 31;
    int n = blockIdx.x * 8 + warp;
    if (n >= NN) return;
    const float* row = g_bufA + (size_t)n * CC;
    #pragma unroll
    for (int h = 0; h < NH; h++) {
        int base = h * FD;
        float s = 0.f, d = 0.f;
        for (int f = lane; f < FD; f += 32) {
            float v = row[base + f];
            s += v * ws[base + f];
            d += v * wd[base + f];
        }
        #pragma unroll
        for (int o = 16; o > 0; o >>= 1) {
            s += __shfl_down_sync(0xffffffffu, s, o);
            d += __shfl_down_sync(0xffffffffu, d, o);
        }
        if (lane == 0) { g_as[n * NH + h] = s; g_ad[n * NH + h] = d; }
    }
}

// ---------------- fused GAT gather: one warp per dst; emits relu'd bf16 hi/lo ----------------
__global__ __launch_bounds__(256)
void k_gat_gather(const float* __restrict__ bias) {
    int w = (blockIdx.x * blockDim.x + threadIdx.x) >> 5;
    if (w >= NN) return;
    int lane = threadIdx.x & 31;
    int beg = g_off[w], end = g_off[w + 1];

    float ad = (lane < NH) ? g_ad[w * NH + lane] : 0.f;

    // pass 1: online softmax (lanes 0..NH-1 own one head each)
    float m = -1e30f, ssum = 0.f;
    for (int j = beg; j < end; j++) {
        int s = g_srccsr[j];
        if (lane < NH) {
            float e = g_as[s * NH + lane] + ad;
            e = (e > 0.f) ? e : 0.2f * e;
            float mn = fmaxf(m, e);
            ssum = ssum * expf(m - mn) + expf(e - mn);
            m = mn;
        }
    }
    float inv = 1.f / (ssum + 1e-16f);

    // pass 2: weighted accumulation; lane owns f = lane + 32*i
    float acc[25];
    #pragma unroll
    for (int i = 0; i < 25; i++) acc[i] = 0.f;

    for (int j = beg; j < end; j++) {
        int s = g_srccsr[j];
        float alpha = 0.f;
        if (lane < NH) {
            float e = g_as[s * NH + lane] + ad;
            e = (e > 0.f) ? e : 0.2f * e;
            alpha = expf(e - m) * inv;
        }
        const float* row = g_bufA + (size_t)s * CC;
        #pragma unroll
        for (int i = 0; i < 25; i++) {
            int f = lane + (i << 5);
            int h = (f < CC ? f : CC - 1) / FD;
            float al = __shfl_sync(0xffffffffu, alpha, h);
            if (f < CC) acc[i] += row[f] * al;
        }
    }
    // fused epilogue: relu(gat_out + bias) -> split bf16 hi/lo (padded row KP2)
    #pragma unroll
    for (int i = 0; i < 25; i++) {
        int f = lane + (i << 5);
        if (f < KP2) {
            float v = 0.f;
            if (f < CC) v = fmaxf(acc[i] + bias[f], 0.f);
            __nv_bfloat16 hi = __float2bfloat16(v);
            g_Ah[(size_t)w * KP2 + f] = hi;
            g_Al[(size_t)w * KP2 + f] = __float2bfloat16(v - __bfloat162float(hi));
        }
    }
}

// ---------------- fused GCN gather: one warp per dst node ----------------
__global__ __launch_bounds__(256)
void k_gcn_gather(const float* __restrict__ bias) {
    int w = (blockIdx.x * blockDim.x + threadIdx.x) >> 5;
    if (w >= NN) return;
    int lane = threadIdx.x & 31;
    int beg = g_off[w], end = g_off[w + 1];
    float dv = g_dinv[w];

    float acc[25];
    #pragma unroll
    for (int i = 0; i < 25; i++) acc[i] = 0.f;

    for (int j = beg; j < end; j++) {
        int s = g_srccsr[j];
        float nr = g_dinv[s] * dv;
        const float* row = g_bufA + (size_t)s * CC;
        #pragma unroll
        for (int i = 0; i < 25; i++) {
            int f = lane + (i << 5);
            if (f < CC) acc[i] += row[f] * nr;
        }
    }
    #pragma unroll
    for (int i = 0; i < 25; i++) {
        int f = lane + (i << 5);
        if (f < CC) g_bufB[(size_t)w * CC + f] = acc[i] + bias[f];
    }
}

// ---------------- pooling (batch sorted -> contiguous ranges) ----------------
__global__ void k_pool2() {
    int b = blockIdx.y;
    int f = blockIdx.x * 256 + threadIdx.x;
    if (f >= CC) return;
    int s = g_bstart[b], e = g_bstart[b + 1];
    float mx = 0.f, sm = 0.f;
    for (int n = s; n < e; n++) {
        float v = fmaxf(g_bufB[(size_t)n * CC + f], 0.f);   // relu(gcn_out)
        mx = fmaxf(mx, v);
        sm += v;
    }
    g_g[b * 1560 + f] = mx;
    g_g[b * 1560 + 780 + f] = sm / fmaxf((float)(e - s), 1.f);
}

// ---------------- protein branches ----------------
__global__ void k_conv2(const int* __restrict__ t2, const float* __restrict__ emb,
                        const float* __restrict__ Wc2, const float* __restrict__ bc2)
{
    __shared__ float wag[26 * 256];
    int b = blockIdx.x;
    int tid = threadIdx.x;
    for (int v = 0; v < 26; v++) wag[v * 256 + tid] = 0.f;
    __syncthreads();
    int o = tid >> 3, k = tid & 7;
    const float* wcol = &Wc2[o * 8000 + k];
    const int* t2b = &t2[b * 1000];
    for (int i = 0; i < 1000; i++) {
        int v = t2b[i];
        wag[v * 256 + tid] += wcol[i * 8];
    }
    __syncthreads();
    for (int j = tid; j < 32 * 121; j += 256) {
        int oo = j / 121, l = j % 121;
        float acc = bc2[oo];
        for (int v = 0; v < 26; v++) {
            const float* wa = &wag[v * 256 + oo * 8];
            const float* er = &emb[v * 128 + l];
            #pragma unroll
            for (int kk = 0; kk < 8; kk++) acc += wa[kk] * er[kk];
        }
        g_xt2c[b * 3872 + j] = acc;
    }
}

__global__ void k_conv1(const float* __restrict__ t1, const float* __restrict__ Wc1,
                        const float* __restrict__ bc1)
{
    int b = blockIdx.x;
    int tid = threadIdx.x;
    int o = tid / 17, l = tid % 17;
    float acc = bc1[o];
    for (int i = 0; i < 20; i++) {
        const float* xr = &t1[b * 480 + i * 24 + l];
        const float* wr = &Wc1[o * 160 + i * 8];
        #pragma unroll
        for (int k = 0; k < 8; k++) acc += xr[k] * wr[k];
    }
    g_xt1c[b * 544 + tid] = acc;
}

// ---------------- launch ----------------
static inline dim3 gemm_grid(int M, int N) {
    return dim3((N + 63) / 64, (M + 63) / 64);
}
static inline dim3 wmma_grid(int M, int N) {
    return dim3((N + 127) / 128, (M + 127) / 128);
}

extern "C" void kernel_launch(void* const* d_in, const int* in_sizes, int n_in,
                              void* d_out, int out_size)
{
    const float* x       = (const float*)d_in[0];
    const int*   ei      = (const int*)  d_in[1];
    const int*   batch   = (const int*)  d_in[2];
    const float* target1 = (const float*)d_in[3];
    const int*   target2 = (const int*)  d_in[4];
    const float* W_gat   = (const float*)d_in[5];
    const float* att_src = (const float*)d_in[6];
    const float* att_dst = (const float*)d_in[7];
    const float* b_gat   = (const float*)d_in[8];
    const float* W_gcn   = (const float*)d_in[9];
    const float* b_gcn   = (const float*)d_in[10];
    const float* W_fcg1  = (const float*)d_in[11];
    const float* b_fcg1  = (const float*)d_in[12];
    const float* W_fcg2  = (const float*)d_in[13];
    const float* b_fcg2  = (const float*)d_in[14];
    const float* emb     = (const float*)d_in[15];
    const float* Wc2     = (const float*)d_in[16];
    const float* bc2     = (const float*)d_in[17];
    const float* W_fc2xt = (const float*)d_in[18];
    const float* b_fc2xt = (const float*)d_in[19];
    const float* Wc1     = (const float*)d_in[20];
    const float* bc1     = (const float*)d_in[21];
    const float* W_fc1xt = (const float*)d_in[22];
    const float* b_fc1xt = (const float*)d_in[23];
    const float* W_fc1   = (const float*)d_in[24];
    const float* b_fc1   = (const float*)d_in[25];
    const float* W_fc2   = (const float*)d_in[26];
    const float* b_fc2   = (const float*)d_in[27];
    const float* W_out   = (const float*)d_in[28];
    const float* b_out   = (const float*)d_in[29];
    float* out = (float*)d_out;

    int E0 = in_sizes[1] / 2;           // 150000
    int E  = E0 + NN;                   // + self loops

    float *bufA, *pg, *pt1, *pxc, *pxt2c, *pxt1c, *pf1, *pf2;
    __nv_bfloat16 *pAh, *pAl, *pBh, *pBl;
    cudaGetSymbolAddress((void**)&bufA,  g_bufA);
    cudaGetSymbolAddress((void**)&pAh,   g_Ah);
    cudaGetSymbolAddress((void**)&pAl,   g_Al);
    cudaGetSymbolAddress((void**)&pBh,   g_Bh);
    cudaGetSymbolAddress((void**)&pBl,   g_Bl);
    cudaGetSymbolAddress((void**)&pg,    g_g);
    cudaGetSymbolAddress((void**)&pt1,   g_t1);
    cudaGetSymbolAddress((void**)&pxc,   g_xc);
    cudaGetSymbolAddress((void**)&pxt2c, g_xt2c);
    cudaGetSymbolAddress((void**)&pxt1c, g_xt1c);
    cudaGetSymbolAddress((void**)&pf1,   g_f1);
    cudaGetSymbolAddress((void**)&pf2,   g_f2);

    // --- CSR + batch boundaries ---
    k_zero_deg<<<(NN + 255) / 256, 256>>>();
    k_count<<<(E + 255) / 256, 256>>>(ei, E0, E);
    k_scan1<<<NBLK, 1024>>>();
    k_scan2<<<1, 64>>>();
    k_scan3<<<(NN + 255) / 256, 256>>>();
    k_prep<<<(NN + 255) / 256, 256>>>();
    k_fillcsr<<<(E + 255) / 256, 256>>>(ei, E0, E);
    k_bstart<<<(NN + 255) / 256, 256>>>(batch);

    // --- h = x @ W_gat (split-bf16 tensor cores) ---
    {
        size_t na = (size_t)NN * KP1;
        k_convA<false><<<(int)((na + 255) / 256), 256>>>(x, NN, FD, KP1, pAh, pAl);
        size_t nb = (size_t)KP1 * NP;
        k_convB<<<(int)((nb + 255) / 256), 256>>>(W_gat, FD, CC, KP1, pBh, pBl);
        wmma_gemm<<<wmma_grid(NN, CC), 256>>>(pAh, pAl, pBh, pBl, bufA, NN, CC, KP1, CC);
    }

    // --- GAT: logits + fused softmax/aggregate gather (emits bf16 hi/lo for GEMM2) ---
    k_compute_a<<<(NN + 7) / 8, 256>>>(att_src, att_dst);
    k_gat_gather<<<(NN * 32 + 255) / 256, 256>>>(b_gat);

    // --- hg = relu(gat_out) @ W_gcn (split-bf16 tensor cores; A already bf16) ---
    {
        size_t nb = (size_t)KP2 * NP;
        k_convB<<<(int)((nb + 255) / 256), 256>>>(W_gcn, CC, CC, KP2, pBh, pBl);
        wmma_gemm<<<wmma_grid(NN, CC), 256>>>(pAh, pAl, pBh, pBl, bufA, NN, CC, KP2, CC);
    }

    // --- GCN gather ---
    k_gcn_gather<<<(NN * 32 + 255) / 256, 256>>>(b_gcn);

    // --- pooling (no atomics; batch sorted) ---
    k_pool2<<<dim3(4, NB), 256>>>();

    // --- graph MLP head ---
    sgemm_kernel<true ><<<gemm_grid(NB, 1500), 256>>>(pg,  W_fcg1, b_fcg1, pt1, NB, 1500, 1560, 1500);
    sgemm_kernel<false><<<gemm_grid(NB, 128),  256>>>(pt1, W_fcg2, b_fcg2, pxc + 0,   NB, 128, 1500, 384);

    // --- protein branches ---
    k_conv2<<<NB, 256>>>(target2, emb, Wc2, bc2);
    sgemm_kernel<false><<<gemm_grid(NB, 128),  256>>>(pxt2c, W_fc2xt, b_fc2xt, pxc + 256, NB, 128, 3872, 384);
    k_conv1<<<NB, 544>>>(target1, Wc1, bc1);
    sgemm_kernel<false><<<gemm_grid(NB, 128),  256>>>(pxt1c, W_fc1xt, b_fc1xt, pxc + 128, NB, 128, 544, 384);

    // --- final MLP ---
    sgemm_kernel<true ><<<gemm_grid(NB, 1024), 256>>>(pxc, W_fc1, b_fc1, pf1, NB, 1024, 384, 1024);
    sgemm_kernel<true ><<<gemm_grid(NB, 512),  256>>>(pf1, W_fc2, b_fc2, pf2, NB, 512, 1024, 512);
    sgemm_kernel<false><<<gemm_grid(NB, 1),    256>>>(pf2, W_out, b_out, out, NB, 1, 512, 1);
}

// round 10
// speedup vs baseline: 2.1963x; 1.0399x over previous
#include <cuda_runtime.h>
#include <cuda_bf16.h>
#include <mma.h>
#include <math.h>
#include <cstdint>

using namespace nvcuda;

// ---------------- problem constants ----------------
#define NN 50000      // nodes
#define NB 128        // graphs / batch
#define NH 10         // heads
#define FD 78         // per-head feature
#define CC 780        // NH*FD
#define E0MAX 150000
#define EMAX  (E0MAX + NN)   // edges incl self loops
#define KP1 96               // GEMM1 K (78) padded to mult of 32
#define KP2 800              // GEMM2 K (780) padded to mult of 32
#define NP  896              // N padded (7*128) for B tiles
#define NBLK 49              // ceil(NN/1024)

// ---------------- scratch (device globals; no allocs) ----------------
__device__ float g_bufA[NN * CC];   // h = x@W_gat, later hg = relu(gat)@W_gcn
__device__ float g_bufB[NN * CC];   // gcn_out
__device__ __nv_bfloat16 g_Ah[NN * KP2];
__device__ __nv_bfloat16 g_Al[NN * KP2];
__device__ __nv_bfloat16 g_Bh[KP2 * NP];
__device__ __nv_bfloat16 g_Bl[KP2 * NP];
__device__ float g_as[NN * NH];
__device__ float g_ad[NN * NH];
__device__ int   g_degi[NN];
__device__ int   g_off[NN + 1];
__device__ int   g_cur[NN];
__device__ int   g_srccsr[EMAX];
__device__ float g_dinv[NN];
__device__ int   g_bstart[NB + 1];
__device__ int   g_bsum[64];
__device__ int   g_bsum2[64];
__device__ float g_g[NB * 1560];
__device__ float g_t1[NB * 1500];
__device__ float g_xc[NB * 384];
__device__ float g_xt2c[NB * 3872];
__device__ float g_xt1c[NB * 544];
__device__ float g_f1[NB * 1024];
__device__ float g_f2[NB * 512];

// ---------------- helpers ----------------
__device__ __forceinline__ void edge_sd(const int* ei, int E0, int e, int& s, int& d) {
    if (e < E0) { s = ei[e]; d = ei[E0 + e]; }
    else        { s = e - E0; d = e - E0; }
}

__device__ __forceinline__ void cp_async16(unsigned int smem, const void* gmem, int srcbytes) {
    asm volatile("cp.async.cg.shared.global [%0], [%1], 16, %2;\n"
                 :: "r"(smem), "l"(gmem), "r"(srcbytes));
}
__device__ __forceinline__ unsigned int smem_u32(const void* p) {
    return (unsigned int)__cvta_generic_to_shared(p);
}

// ---------------- CSR build ----------------
__global__ void k_zero_deg() {
    int i = blockIdx.x * blockDim.x + threadIdx.x;
    if (i < NN) g_degi[i] = 0;
}

__global__ void k_count(const int* __restrict__ ei, int E0, int E) {
    int e = blockIdx.x * blockDim.x + threadIdx.x;
    if (e >= E) return;
    int s, d; edge_sd(ei, E0, e, s, d);
    (void)s;
    atomicAdd(&g_degi[d], 1);
}

__global__ void k_scan1() {
    __shared__ int sh[1024];
    int tid = threadIdx.x;
    int i = blockIdx.x * 1024 + tid;
    int v = (i < NN) ? g_degi[i] : 0;
    sh[tid] = v;
    __syncthreads();
    #pragma unroll
    for (int o = 1; o < 1024; o <<= 1) {
        int t = (tid >= o) ? sh[tid - o] : 0;
        __syncthreads();
        sh[tid] += t;
        __syncthreads();
    }
    if (i < NN) g_off[i] = sh[tid] - v;      // block-local exclusive
    if (tid == 1023) g_bsum[blockIdx.x] = sh[1023];
}

__global__ void k_scan2() {
    __shared__ int sh[64];
    int t = threadIdx.x;
    int v = (t < NBLK) ? g_bsum[t] : 0;
    sh[t] = v;
    __syncthreads();
    #pragma unroll
    for (int o = 1; o < 64; o <<= 1) {
        int x = (t >= o) ? sh[t - o] : 0;
        __syncthreads();
        sh[t] += x;
        __syncthreads();
    }
    if (t < NBLK) g_bsum2[t] = sh[t] - v;    // exclusive
    if (t == 63) g_off[NN] = sh[63];         // total
}

__global__ void k_scan3() {
    int i = blockIdx.x * blockDim.x + threadIdx.x;
    if (i < NN) g_off[i] += g_bsum2[i >> 10];
}

__global__ void k_prep() {
    int n = blockIdx.x * blockDim.x + threadIdx.x;
    if (n >= NN) return;
    g_cur[n] = g_off[n];
    float dg = (float)g_degi[n];
    g_dinv[n] = (dg > 0.f) ? rsqrtf(dg) : 0.f;
}

__global__ void k_fillcsr(const int* __restrict__ ei, int E0, int E) {
    int e = blockIdx.x * blockDim.x + threadIdx.x;
    if (e >= E) return;
    int s, d; edge_sd(ei, E0, e, s, d);
    int pos = atomicAdd(&g_cur[d], 1);
    g_srccsr[pos] = s;
}

__global__ void k_bstart(const int* __restrict__ batch) {
    int n = blockIdx.x * blockDim.x + threadIdx.x;
    if (n >= NN) return;
    int bn = batch[n];
    int bp = (n == 0) ? -1 : batch[n - 1];
    for (int g = bp + 1; g <= bn; g++) g_bstart[g] = n;
    if (n == NN - 1)
        for (int g = bn + 1; g <= NB; g++) g_bstart[g] = NN;
}

// ---------------- split-bf16 conversion ----------------
template<bool RELU>
__global__ void k_convA(const float* __restrict__ src, int M, int K, int Kp,
                        __nv_bfloat16* __restrict__ Ah, __nv_bfloat16* __restrict__ Al)
{
    size_t idx = (size_t)blockIdx.x * blockDim.x + threadIdx.x;
    if (idx >= (size_t)M * Kp) return;
    int c = (int)(idx % Kp);
    int r = (int)(idx / Kp);
    float v = 0.f;
    if (c < K) {
        v = src[(size_t)r * K + c];
        if (RELU) v = fmaxf(v, 0.f);
    }
    __nv_bfloat16 h = __float2bfloat16(v);
    Ah[idx] = h;
    Al[idx] = __float2bfloat16(v - __bfloat162float(h));
}

// B stored [k][NP] row-major, zero-padded columns/rows
__global__ void k_convB(const float* __restrict__ W, int K, int N, int Kp,
                        __nv_bfloat16* __restrict__ Bh, __nv_bfloat16* __restrict__ Bl)
{
    size_t idx = (size_t)blockIdx.x * blockDim.x + threadIdx.x;
    if (idx >= (size_t)Kp * NP) return;
    int n = (int)(idx % NP);
    int k = (int)(idx / NP);
    float v = (k < K && n < N) ? W[(size_t)k * N + n] : 0.f;
    __nv_bfloat16 h = __float2bfloat16(v);
    Bh[idx] = h;
    Bl[idx] = __float2bfloat16(v - __bfloat162float(h));
}

// ---------------- split-bf16 wmma GEMM v3 (BK=32, dynamic smem) ----------------
// A: [M, Kp] hi/lo row-major.  B: [Kp, NP] hi/lo row-major (zero-padded).
// C: fp32 [M, ldc].  Block tile 128x128, 8 warps (4M x 2N), warp tile 32x64.
#define ALD 40      // A smem row stride (elems): 80B rows, conflict-free LDSM
#define BLD 136     // B smem row stride: 272B rows, conflict-free LDSM
#define AH_OFF 0
#define AL_OFF (128 * ALD)                       // 5120
#define BH_OFF (2 * 128 * ALD)                   // 10240
#define BL_OFF (2 * 128 * ALD + 32 * BLD)        // 14592
#define STAGE_EL (2 * 128 * ALD + 2 * 32 * BLD)  // 18944 elems / stage
#define WG_SMEM (2 * STAGE_EL * 2)               // 75776 bytes

__global__ __launch_bounds__(256, 2)
void wmma_gemm(const __nv_bfloat16* __restrict__ Ah, const __nv_bfloat16* __restrict__ Al,
               const __nv_bfloat16* __restrict__ Bh, const __nv_bfloat16* __restrict__ Bl,
               float* __restrict__ C, int M, int N, int Kp, int ldc)
{
    extern __shared__ __align__(16) __nv_bfloat16 sm[];

    int tid = threadIdx.x;
    int wid = tid >> 5, lane = tid & 31;
    int wm = wid & 3, wn = wid >> 2;
    int brow = blockIdx.y * 128, bcol = blockIdx.x * 128;
    int ns = Kp >> 5;

    wmma::fragment<wmma::accumulator, 16, 16, 16, float> acc[2][4];
    #pragma unroll
    for (int i = 0; i < 2; i++)
        #pragma unroll
        for (int j = 0; j < 4; j++) wmma::fill_fragment(acc[i][j], 0.f);

    // slab loader: A 128x32 hi+lo (16KB) + B 32x128 hi+lo (16KB), 2048 chunks
    auto load_slab = [&](int k0, int buf) {
        __nv_bfloat16* base = sm + buf * STAGE_EL;
        #pragma unroll
        for (int q = 0; q < 4; q++) {
            int a = tid + (q << 8);                 // 0..1023
            int row = a >> 3, c3 = a & 7, part = c3 >> 2, seg = c3 & 3;
            int gm = brow + row;
            const __nv_bfloat16* srcb = part ? Al : Ah;
            const void* src = (gm < M) ? (const void*)(srcb + (size_t)gm * Kp + k0 + seg * 8)
                                       : (const void*)srcb;
            unsigned int dst = smem_u32(base + (part ? AL_OFF : AH_OFF) + row * ALD + seg * 8);
            cp_async16(dst, src, (gm < M) ? 16 : 0);
        }
        #pragma unroll
        for (int q = 0; q < 4; q++) {
            int b = tid + (q << 8);                 // 0..1023
            int k = b >> 5, c5 = b & 31, part = c5 >> 4, cs = c5 & 15;
            const __nv_bfloat16* srcb = part ? Bl : Bh;
            const void* src = srcb + (size_t)(k0 + k) * NP + bcol + cs * 8;  // NP-padded
            unsigned int dst = smem_u32(base + (part ? BL_OFF : BH_OFF) + k * BLD + cs * 8);
            cp_async16(dst, src, 16);
        }
        asm volatile("cp.async.commit_group;\n");
    };

    load_slab(0, 0);

    for (int it = 0; it < ns; it++) {
        int buf = it & 1;
        if (it + 1 < ns) {
            load_slab((it + 1) << 5, buf ^ 1);
            asm volatile("cp.async.wait_group 1;\n");
        } else {
            asm volatile("cp.async.wait_group 0;\n");
        }
        __syncthreads();

        __nv_bfloat16* base = sm + buf * STAGE_EL;
        #pragma unroll
        for (int ks = 0; ks < 2; ks++) {
            wmma::fragment<wmma::matrix_a, 16, 16, 16, __nv_bfloat16, wmma::row_major> ah[2], al[2];
            #pragma unroll
            for (int i = 0; i < 2; i++) {
                wmma::load_matrix_sync(ah[i], base + AH_OFF + (wm * 32 + i * 16) * ALD + ks * 16, ALD);
                wmma::load_matrix_sync(al[i], base + AL_OFF + (wm * 32 + i * 16) * ALD + ks * 16, ALD);
            }
            #pragma unroll
            for (int j = 0; j < 4; j++) {
                wmma::fragment<wmma::matrix_b, 16, 16, 16, __nv_bfloat16, wmma::row_major> bh, bl;
                wmma::load_matrix_sync(bh, base + BH_OFF + ks * 16 * BLD + wn * 64 + j * 16, BLD);
                wmma::load_matrix_sync(bl, base + BL_OFF + ks * 16 * BLD + wn * 64 + j * 16, BLD);
                #pragma unroll
                for (int i = 0; i < 2; i++) {
                    wmma::mma_sync(acc[i][j], ah[i], bh, acc[i][j]);
                    wmma::mma_sync(acc[i][j], ah[i], bl, acc[i][j]);
                    wmma::mma_sync(acc[i][j], al[i], bh, acc[i][j]);
                }
            }
        }
        __syncthreads();
    }

    // ---- epilogue ----
    if (brow + 128 <= M && bcol + 128 <= N) {
        #pragma unroll
        for (int i = 0; i < 2; i++)
            #pragma unroll
            for (int j = 0; j < 4; j++) {
                int gm0 = brow + wm * 32 + i * 16;
                int gn0 = bcol + wn * 64 + j * 16;
                wmma::store_matrix_sync(&C[(size_t)gm0 * ldc + gn0], acc[i][j], ldc,
                                        wmma::mem_row_major);
            }
    } else {
        float* stagep = (float*)sm + wid * 272;
        __syncthreads();
        #pragma unroll
        for (int i = 0; i < 2; i++)
            #pragma unroll
            for (int j = 0; j < 4; j++) {
                wmma::store_matrix_sync(stagep, acc[i][j], 16, wmma::mem_row_major);
                __syncwarp();
                int gm0 = brow + wm * 32 + i * 16;
                int gn0 = bcol + wn * 64 + j * 16;
                for (int e = lane; e < 256; e += 32) {
                    int r = e >> 4, c = e & 15;
                    int gm = gm0 + r, gn = gn0 + c;
                    if (gm < M && gn < N) C[(size_t)gm * ldc + gn] = stagep[r * 16 + c];
                }
                __syncwarp();
            }
    }
}

// ---------------- fp32 tiled SGEMM for the small FC head ----------------
template<bool RELU_OUT>
__global__ void sgemm_kernel(const float* __restrict__ A, const float* __restrict__ B,
                             const float* __restrict__ bias, float* __restrict__ C,
                             int M, int N, int K, int ldc)
{
    const int BM = 64, BN = 64, BK = 16;
    __shared__ float As[BK][BM + 1];
    __shared__ float Bs[BK][BN + 1];
    int tid = threadIdx.x;
    int tx = tid & 15, ty = tid >> 4;
    int brow = blockIdx.y * BM;
    int bcol = blockIdx.x * BN;

    float acc[4][4];
    #pragma unroll
    for (int i = 0; i < 4; i++)
        #pragma unroll
        for (int j = 0; j < 4; j++) acc[i][j] = 0.f;

    for (int k0 = 0; k0 < K; k0 += BK) {
        #pragma unroll
        for (int i = 0; i < 4; i++) {
            int idx = tid + i * 256;
            int m = idx >> 4, k = idx & 15;
            int gm = brow + m, gk = k0 + k;
            As[k][m] = (gm < M && gk < K) ? A[(size_t)gm * K + gk] : 0.f;
        }
        #pragma unroll
        for (int i = 0; i < 4; i++) {
            int idx = tid + i * 256;
            int k = idx >> 6, n = idx & 63;
            int gk = k0 + k, gn = bcol + n;
            Bs[k][n] = (gk < K && gn < N) ? B[(size_t)gk * N + gn] : 0.f;
        }
        __syncthreads();
        #pragma unroll
        for (int kk = 0; kk < BK; kk++) {
            float a[4], b[4];
            #pragma unroll
            for (int i = 0; i < 4; i++) a[i] = As[kk][ty * 4 + i];
            #pragma unroll
            for (int j = 0; j < 4; j++) b[j] = Bs[kk][tx * 4 + j];
            #pragma unroll
            for (int i = 0; i < 4; i++)
                #pragma unroll
                for (int j = 0; j < 4; j++) acc[i][j] += a[i] * b[j];
        }
        __syncthreads();
    }
    #pragma unroll
    for (int i = 0; i < 4; i++) {
        int gm = brow + ty * 4 + i;
        if (gm >= M) continue;
        #pragma unroll
        for (int j = 0; j < 4; j++) {
            int gn = bcol + tx * 4 + j;
            if (gn >= N) continue;
            float v = acc[i][j] + (bias ? bias[gn] : 0.f);
            if (RELU_OUT) v = fmaxf(v, 0.f);
            C[(size_t)gm * ldc + gn] = v;
        }
    }
}

// ---------------- attention logits: warp per node, coalesced ----------------
__global__ __launch_bounds__(256)
void k_compute_a(const float* __restrict__ att_src, const float* __restrict__ att_dst) {
    __shared__ float ws[CC], wd[CC];
    for (int i = threadIdx.x; i < CC; i += 256) { ws[i] = att_src[i]; wd[i] = att_dst[i]; }
    __syncthreads();
    int warp = threadIdx.x >> 5, lane = threadIdx.x & 31;
    int n = blockIdx.x * 8 + warp;
    if (n >= NN) return;
    const float* row = g_bufA + (size_t)n * CC;
    #pragma unroll
    for (int h = 0; h < NH; h++) {
        int base = h * FD;
        float s = 0.f, d = 0.f;
        for (int f = lane; f < FD; f += 32) {
            float v = row[base + f];
            s += v * ws[base + f];
            d += v * wd[base + f];
        }
        #pragma unroll
        for (int o = 16; o > 0; o >>= 1) {
            s += __shfl_down_sync(0xffffffffu, s, o);
            d += __shfl_down_sync(0xffffffffu, d, o);
        }
        if (lane == 0) { g_as[n * NH + h] = s; g_ad[n * NH + h] = d; }
    }
}

// ---------------- fused GAT gather: one warp per dst; float4 rows; emits bf16 hi/lo ----------------
__global__ __launch_bounds__(256)
void k_gat_gather(const float* __restrict__ bias) {
    int w = (blockIdx.x * blockDim.x + threadIdx.x) >> 5;
    if (w >= NN) return;
    int lane = threadIdx.x & 31;
    int beg = g_off[w], end = g_off[w + 1];

    float ad = (lane < NH) ? g_ad[w * NH + lane] : 0.f;

    // pass 1: online softmax (lanes 0..NH-1 own one head each)
    float m = -1e30f, ssum = 0.f;
    for (int j = beg; j < end; j++) {
        int s = g_srccsr[j];
        if (lane < NH) {
            float e = g_as[s * NH + lane] + ad;
            e = (e > 0.f) ? e : 0.2f * e;
            float mn = fmaxf(m, e);
            ssum = ssum * expf(m - mn) + expf(e - mn);
            m = mn;
        }
    }
    float inv = 1.f / (ssum + 1e-16f);

    // precompute per-element head index (loop-invariant)
    int hidx[7][4];
    #pragma unroll
    for (int j = 0; j < 7; j++)
        #pragma unroll
        for (int c = 0; c < 4; c++) {
            int f = 4 * (lane + (j << 5)) + c;
            hidx[j][c] = (f < CC ? f : CC - 1) / FD;
        }

    // pass 2: weighted accumulation; lane owns float4 q = lane + 32*j (q < 195)
    float4 acc4[7];
    #pragma unroll
    for (int j = 0; j < 7; j++) acc4[j] = make_float4(0.f, 0.f, 0.f, 0.f);

    for (int j = beg; j < end; j++) {
        int s = g_srccsr[j];
        float alpha = 0.f;
        if (lane < NH) {
            float e = g_as[s * NH + lane] + ad;
            e = (e > 0.f) ? e : 0.2f * e;
            alpha = expf(e - m) * inv;
        }
        const float4* row4 = (const float4*)(g_bufA + (size_t)s * CC);
        #pragma unroll
        for (int i = 0; i < 7; i++) {
            float a0 = __shfl_sync(0xffffffffu, alpha, hidx[i][0]);
            float a1 = __shfl_sync(0xffffffffu, alpha, hidx[i][1]);
            float a2 = __shfl_sync(0xffffffffu, alpha, hidx[i][2]);
            float a3 = __shfl_sync(0xffffffffu, alpha, hidx[i][3]);
            int q = lane + (i << 5);
            if (q < CC / 4) {
                float4 v = row4[q];
                acc4[i].x += v.x * a0;
                acc4[i].y += v.y * a1;
                acc4[i].z += v.z * a2;
                acc4[i].w += v.w * a3;
            }
        }
    }
    // fused epilogue: relu(gat_out + bias) -> split bf16 hi/lo (row stride KP2)
    #pragma unroll
    for (int i = 0; i < 7; i++) {
        int q = lane + (i << 5);
        if (q < CC / 4) {
            int f0 = q * 4;
            float vv[4] = {acc4[i].x, acc4[i].y, acc4[i].z, acc4[i].w};
            #pragma unroll
            for (int c = 0; c < 4; c++) {
                float v = fmaxf(vv[c] + bias[f0 + c], 0.f);
                __nv_bfloat16 hi = __float2bfloat16(v);
                g_Ah[(size_t)w * KP2 + f0 + c] = hi;
                g_Al[(size_t)w * KP2 + f0 + c] = __float2bfloat16(v - __bfloat162float(hi));
            }
        }
    }
    // zero-fill K padding [780, 800)
    if (lane < KP2 - CC) {
        int f = CC + lane;
        g_Ah[(size_t)w * KP2 + f] = __float2bfloat16(0.f);
        g_Al[(size_t)w * KP2 + f] = __float2bfloat16(0.f);
    }
}

// ---------------- fused GCN gather: one warp per dst node, float4 ----------------
__global__ __launch_bounds__(256)
void k_gcn_gather(const float* __restrict__ bias) {
    int w = (blockIdx.x * blockDim.x + threadIdx.x) >> 5;
    if (w >= NN) return;
    int lane = threadIdx.x & 31;
    int beg = g_off[w], end = g_off[w + 1];
    float dv = g_dinv[w];

    float4 acc4[7];
    #pragma unroll
    for (int i = 0; i < 7; i++) acc4[i] = make_float4(0.f, 0.f, 0.f, 0.f);

    for (int j = beg; j < end; j++) {
        int s = g_srccsr[j];
        float nr = g_dinv[s] * dv;
        const float4* row4 = (const float4*)(g_bufA + (size_t)s * CC);
        #pragma unroll
        for (int i = 0; i < 7; i++) {
            int q = lane + (i << 5);
            if (q < CC / 4) {
                float4 v = row4[q];
                acc4[i].x += v.x * nr;
                acc4[i].y += v.y * nr;
                acc4[i].z += v.z * nr;
                acc4[i].w += v.w * nr;
            }
        }
    }
    const float4* bias4 = (const float4*)bias;
    float4* out4 = (float4*)(g_bufB + (size_t)w * CC);
    #pragma unroll
    for (int i = 0; i < 7; i++) {
        int q = lane + (i << 5);
        if (q < CC / 4) {
            float4 b = bias4[q];
            float4 o;
            o.x = acc4[i].x + b.x;
            o.y = acc4[i].y + b.y;
            o.z = acc4[i].z + b.z;
            o.w = acc4[i].w + b.w;
            out4[q] = o;
        }
    }
}

// ---------------- pooling (batch sorted -> contiguous ranges) ----------------
__global__ void k_pool2() {
    int b = blockIdx.y;
    int f = blockIdx.x * 256 + threadIdx.x;
    if (f >= CC) return;
    int s = g_bstart[b], e = g_bstart[b + 1];
    float mx = 0.f, sm = 0.f;
    for (int n = s; n < e; n++) {
        float v = fmaxf(g_bufB[(size_t)n * CC + f], 0.f);   // relu(gcn_out)
        mx = fmaxf(mx, v);
        sm += v;
    }
    g_g[b * 1560 + f] = mx;
    g_g[b * 1560 + 780 + f] = sm / fmaxf((float)(e - s), 1.f);
}

// ---------------- protein branches ----------------
__global__ void k_conv2(const int* __restrict__ t2, const float* __restrict__ emb,
                        const float* __restrict__ Wc2, const float* __restrict__ bc2)
{
    __shared__ float wag[26 * 256];
    int b = blockIdx.x;
    int tid = threadIdx.x;
    for (int v = 0; v < 26; v++) wag[v * 256 + tid] = 0.f;
    __syncthreads();
    int o = tid >> 3, k = tid & 7;
    const float* wcol = &Wc2[o * 8000 + k];
    const int* t2b = &t2[b * 1000];
    for (int i = 0; i < 1000; i++) {
        int v = t2b[i];
        wag[v * 256 + tid] += wcol[i * 8];
    }
    __syncthreads();
    for (int j = tid; j < 32 * 121; j += 256) {
        int oo = j / 121, l = j % 121;
        float acc = bc2[oo];
        for (int v = 0; v < 26; v++) {
            const float* wa = &wag[v * 256 + oo * 8];
            const float* er = &emb[v * 128 + l];
            #pragma unroll
            for (int kk = 0; kk < 8; kk++) acc += wa[kk] * er[kk];
        }
        g_xt2c[b * 3872 + j] = acc;
    }
}

__global__ void k_conv1(const float* __restrict__ t1, const float* __restrict__ Wc1,
                        const float* __restrict__ bc1)
{
    int b = blockIdx.x;
    int tid = threadIdx.x;
    int o = tid / 17, l = tid % 17;
    float acc = bc1[o];
    for (int i = 0; i < 20; i++) {
        const float* xr = &t1[b * 480 + i * 24 + l];
        const float* wr = &Wc1[o * 160 + i * 8];
        #pragma unroll
        for (int k = 0; k < 8; k++) acc += xr[k] * wr[k];
    }
    g_xt1c[b * 544 + tid] = acc;
}

// ---------------- launch ----------------
static inline dim3 gemm_grid(int M, int N) {
    return dim3((N + 63) / 64, (M + 63) / 64);
}

extern "C" void kernel_launch(void* const* d_in, const int* in_sizes, int n_in,
                              void* d_out, int out_size)
{
    const float* x       = (const float*)d_in[0];
    const int*   ei      = (const int*)  d_in[1];
    const int*   batch   = (const int*)  d_in[2];
    const float* target1 = (const float*)d_in[3];
    const int*   target2 = (const int*)  d_in[4];
    const float* W_gat   = (const float*)d_in[5];
    const float* att_src = (const float*)d_in[6];
    const float* att_dst = (const float*)d_in[7];
    const float* b_gat   = (const float*)d_in[8];
    const float* W_gcn   = (const float*)d_in[9];
    const float* b_gcn   = (const float*)d_in[10];
    const float* W_fcg1  = (const float*)d_in[11];
    const float* b_fcg1  = (const float*)d_in[12];
    const float* W_fcg2  = (const float*)d_in[13];
    const float* b_fcg2  = (const float*)d_in[14];
    const float* emb     = (const float*)d_in[15];
    const float* Wc2     = (const float*)d_in[16];
    const float* bc2     = (const float*)d_in[17];
    const float* W_fc2xt = (const float*)d_in[18];
    const float* b_fc2xt = (const float*)d_in[19];
    const float* Wc1     = (const float*)d_in[20];
    const float* bc1     = (const float*)d_in[21];
    const float* W_fc1xt = (const float*)d_in[22];
    const float* b_fc1xt = (const float*)d_in[23];
    const float* W_fc1   = (const float*)d_in[24];
    const float* b_fc1   = (const float*)d_in[25];
    const float* W_fc2   = (const float*)d_in[26];
    const float* b_fc2   = (const float*)d_in[27];
    const float* W_out   = (const float*)d_in[28];
    const float* b_out   = (const float*)d_in[29];
    float* out = (float*)d_out;

    int E0 = in_sizes[1] / 2;           // 150000
    int E  = E0 + NN;                   // + self loops

    cudaFuncSetAttribute(wmma_gemm, cudaFuncAttributeMaxDynamicSharedMemorySize, WG_SMEM);

    float *bufA, *pg, *pt1, *pxc, *pxt2c, *pxt1c, *pf1, *pf2;
    __nv_bfloat16 *pAh, *pAl, *pBh, *pBl;
    cudaGetSymbolAddress((void**)&bufA,  g_bufA);
    cudaGetSymbolAddress((void**)&pAh,   g_Ah);
    cudaGetSymbolAddress((void**)&pAl,   g_Al);
    cudaGetSymbolAddress((void**)&pBh,   g_Bh);
    cudaGetSymbolAddress((void**)&pBl,   g_Bl);
    cudaGetSymbolAddress((void**)&pg,    g_g);
    cudaGetSymbolAddress((void**)&pt1,   g_t1);
    cudaGetSymbolAddress((void**)&pxc,   g_xc);
    cudaGetSymbolAddress((void**)&pxt2c, g_xt2c);
    cudaGetSymbolAddress((void**)&pxt1c, g_xt1c);
    cudaGetSymbolAddress((void**)&pf1,   g_f1);
    cudaGetSymbolAddress((void**)&pf2,   g_f2);

    dim3 wg_grid(7, (NN + 127) / 128);   // N tiles x M tiles

    // --- CSR + batch boundaries ---
    k_zero_deg<<<(NN + 255) / 256, 256>>>();
    k_count<<<(E + 255) / 256, 256>>>(ei, E0, E);
    k_scan1<<<NBLK, 1024>>>();
    k_scan2<<<1, 64>>>();
    k_scan3<<<(NN + 255) / 256, 256>>>();
    k_prep<<<(NN + 255) / 256, 256>>>();
    k_fillcsr<<<(E + 255) / 256, 256>>>(ei, E0, E);
    k_bstart<<<(NN + 255) / 256, 256>>>(batch);

    // --- h = x @ W_gat (split-bf16 wmma) ---
    {
        size_t na = (size_t)NN * KP1;
        k_convA<false><<<(int)((na + 255) / 256), 256>>>(x, NN, FD, KP1, pAh, pAl);
        size_t nb = (size_t)KP1 * NP;
        k_convB<<<(int)((nb + 255) / 256), 256>>>(W_gat, FD, CC, KP1, pBh, pBl);
        wmma_gemm<<<wg_grid, 256, WG_SMEM>>>(pAh, pAl, pBh, pBl, bufA, NN, CC, KP1, CC);
    }

    // --- GAT: logits + fused softmax/aggregate gather (emits bf16 hi/lo for GEMM2) ---
    k_compute_a<<<(NN + 7) / 8, 256>>>(att_src, att_dst);
    k_gat_gather<<<(NN * 32 + 255) / 256, 256>>>(b_gat);

    // --- hg = relu(gat_out) @ W_gcn (split-bf16 wmma; A already bf16) ---
    {
        size_t nb = (size_t)KP2 * NP;
        k_convB<<<(int)((nb + 255) / 256), 256>>>(W_gcn, CC, CC, KP2, pBh, pBl);
        wmma_gemm<<<wg_grid, 256, WG_SMEM>>>(pAh, pAl, pBh, pBl, bufA, NN, CC, KP2, CC);
    }

    // --- GCN gather ---
    k_gcn_gather<<<(NN * 32 + 255) / 256, 256>>>(b_gcn);

    // --- pooling (no atomics; batch sorted) ---
    k_pool2<<<dim3(4, NB), 256>>>();

    // --- graph MLP head ---
    sgemm_kernel<true ><<<gemm_grid(NB, 1500), 256>>>(pg,  W_fcg1, b_fcg1, pt1, NB, 1500, 1560, 1500);
    sgemm_kernel<false><<<gemm_grid(NB, 128),  256>>>(pt1, W_fcg2, b_fcg2, pxc + 0,   NB, 128, 1500, 384);

    // --- protein branches ---
    k_conv2<<<NB, 256>>>(target2, emb, Wc2, bc2);
    sgemm_kernel<false><<<gemm_grid(NB, 128),  256>>>(pxt2c, W_fc2xt, b_fc2xt, pxc + 256, NB, 128, 3872, 384);
    k_conv1<<<NB, 544>>>(target1, Wc1, bc1);
    sgemm_kernel<false><<<gemm_grid(NB, 128),  256>>>(pxt1c, W_fc1xt, b_fc1xt, pxc + 128, NB, 128, 544, 384);

    // --- final MLP ---
    sgemm_kernel<true ><<<gemm_grid(NB, 1024), 256>>>(pxc, W_fc1, b_fc1, pf1, NB, 1024, 384, 1024);
    sgemm_kernel<true ><<<gemm_grid(NB, 512),  256>>>(pf1, W_fc2, b_fc2, pf2, NB, 512, 1024, 512);
    sgemm_kernel<false><<<gemm_grid(NB, 1),    256>>>(pf2, W_out, b_out, out, NB, 1, 512, 1);
}

// round 11
// speedup vs baseline: 2.8465x; 1.2961x over previous
#include <cuda_runtime.h>
#include <cuda_bf16.h>
#include <mma.h>
#include <math.h>
#include <cstdint>

using namespace nvcuda;

// ---------------- problem constants ----------------
#define NN 50000      // nodes
#define NB 128        // graphs / batch
#define NH 10         // heads
#define FD 78         // per-head feature
#define CC 780        // NH*FD
#define E0MAX 150000
#define EMAX  (E0MAX + NN)   // edges incl self loops
#define KP1 96               // GEMM1 K (78) padded to mult of 32
#define KP2 800              // GEMM2 K (780) padded to mult of 32
#define NP  896              // N padded (7*128) for B tiles
#define NBLK 49              // ceil(NN/1024)

// ---------------- scratch (device globals; no allocs) ----------------
__device__ float g_bufA[NN * CC];   // h = x@W_gat, later hg = relu(gat)@W_gcn
__device__ float g_bufB[NN * CC];   // gcn_out
__device__ __nv_bfloat16 g_Ah[NN * KP2];
__device__ __nv_bfloat16 g_Al[NN * KP2];
__device__ __nv_bfloat16 g_Bh1[KP1 * NP];   // GEMM1 B (separate so convB2 can overlap)
__device__ __nv_bfloat16 g_Bl1[KP1 * NP];
__device__ __nv_bfloat16 g_Bh2[KP2 * NP];   // GEMM2 B
__device__ __nv_bfloat16 g_Bl2[KP2 * NP];
__device__ float g_as[NN * NH];
__device__ float g_ad[NN * NH];
__device__ int   g_degi[NN];
__device__ int   g_off[NN + 1];
__device__ int   g_cur[NN];
__device__ int   g_srccsr[EMAX];
__device__ float g_dinv[NN];
__device__ int   g_bstart[NB + 1];
__device__ int   g_bsum[64];
__device__ int   g_bsum2[64];
__device__ float g_g[NB * 1560];
__device__ float g_t1[NB * 1500];
__device__ float g_xc[NB * 384];
__device__ float g_xt2c[NB * 3872];
__device__ float g_xt1c[NB * 544];
__device__ float g_f1[NB * 1024];
__device__ float g_f2[NB * 512];

// ---------------- helpers ----------------
__device__ __forceinline__ void edge_sd(const int* ei, int E0, int e, int& s, int& d) {
    if (e < E0) { s = ei[e]; d = ei[E0 + e]; }
    else        { s = e - E0; d = e - E0; }
}

__device__ __forceinline__ void cp_async16(unsigned int smem, const void* gmem, int srcbytes) {
    asm volatile("cp.async.cg.shared.global [%0], [%1], 16, %2;\n"
                 :: "r"(smem), "l"(gmem), "r"(srcbytes));
}
__device__ __forceinline__ unsigned int smem_u32(const void* p) {
    return (unsigned int)__cvta_generic_to_shared(p);
}

// ---------------- CSR build ----------------
__global__ void k_zero_deg() {
    int i = blockIdx.x * blockDim.x + threadIdx.x;
    if (i < NN) g_degi[i] = 0;
}

__global__ void k_count(const int* __restrict__ ei, int E0, int E) {
    int e = blockIdx.x * blockDim.x + threadIdx.x;
    if (e >= E) return;
    int s, d; edge_sd(ei, E0, e, s, d);
    (void)s;
    atomicAdd(&g_degi[d], 1);
}

__global__ void k_scan1() {
    __shared__ int sh[1024];
    int tid = threadIdx.x;
    int i = blockIdx.x * 1024 + tid;
    int v = (i < NN) ? g_degi[i] : 0;
    sh[tid] = v;
    __syncthreads();
    #pragma unroll
    for (int o = 1; o < 1024; o <<= 1) {
        int t = (tid >= o) ? sh[tid - o] : 0;
        __syncthreads();
        sh[tid] += t;
        __syncthreads();
    }
    if (i < NN) g_off[i] = sh[tid] - v;      // block-local exclusive
    if (tid == 1023) g_bsum[blockIdx.x] = sh[1023];
}

__global__ void k_scan2() {
    __shared__ int sh[64];
    int t = threadIdx.x;
    int v = (t < NBLK) ? g_bsum[t] : 0;
    sh[t] = v;
    __syncthreads();
    #pragma unroll
    for (int o = 1; o < 64; o <<= 1) {
        int x = (t >= o) ? sh[t - o] : 0;
        __syncthreads();
        sh[t] += x;
        __syncthreads();
    }
    if (t < NBLK) g_bsum2[t] = sh[t] - v;    // exclusive
    if (t == 63) g_off[NN] = sh[63];         // total
}

// fused: finalize offsets + init cursors + dinv
__global__ void k_scan3() {
    int i = blockIdx.x * blockDim.x + threadIdx.x;
    if (i >= NN) return;
    int off = g_off[i] + g_bsum2[i >> 10];
    g_off[i] = off;
    g_cur[i] = off;
    float dg = (float)g_degi[i];
    g_dinv[i] = (dg > 0.f) ? rsqrtf(dg) : 0.f;
}

__global__ void k_fillcsr(const int* __restrict__ ei, int E0, int E) {
    int e = blockIdx.x * blockDim.x + threadIdx.x;
    if (e >= E) return;
    int s, d; edge_sd(ei, E0, e, s, d);
    int pos = atomicAdd(&g_cur[d], 1);
    g_srccsr[pos] = s;
}

__global__ void k_bstart(const int* __restrict__ batch) {
    int n = blockIdx.x * blockDim.x + threadIdx.x;
    if (n >= NN) return;
    int bn = batch[n];
    int bp = (n == 0) ? -1 : batch[n - 1];
    for (int g = bp + 1; g <= bn; g++) g_bstart[g] = n;
    if (n == NN - 1)
        for (int g = bn + 1; g <= NB; g++) g_bstart[g] = NN;
}

// ---------------- split-bf16 conversion ----------------
template<bool RELU>
__global__ void k_convA(const float* __restrict__ src, int M, int K, int Kp,
                        __nv_bfloat16* __restrict__ Ah, __nv_bfloat16* __restrict__ Al)
{
    size_t idx = (size_t)blockIdx.x * blockDim.x + threadIdx.x;
    if (idx >= (size_t)M * Kp) return;
    int c = (int)(idx % Kp);
    int r = (int)(idx / Kp);
    float v = 0.f;
    if (c < K) {
        v = src[(size_t)r * K + c];
        if (RELU) v = fmaxf(v, 0.f);
    }
    __nv_bfloat16 h = __float2bfloat16(v);
    Ah[idx] = h;
    Al[idx] = __float2bfloat16(v - __bfloat162float(h));
}

// B stored [k][NP] row-major, zero-padded columns/rows
__global__ void k_convB(const float* __restrict__ W, int K, int N, int Kp,
                        __nv_bfloat16* __restrict__ Bh, __nv_bfloat16* __restrict__ Bl)
{
    size_t idx = (size_t)blockIdx.x * blockDim.x + threadIdx.x;
    if (idx >= (size_t)Kp * NP) return;
    int n = (int)(idx % NP);
    int k = (int)(idx / NP);
    float v = (k < K && n < N) ? W[(size_t)k * N + n] : 0.f;
    __nv_bfloat16 h = __float2bfloat16(v);
    Bh[idx] = h;
    Bl[idx] = __float2bfloat16(v - __bfloat162float(h));
}

// ---------------- split-bf16 wmma GEMM v3 (BK=32, dynamic smem) ----------------
#define ALD 40      // A smem row stride (elems): 80B rows, conflict-free LDSM
#define BLD 136     // B smem row stride: 272B rows, conflict-free LDSM
#define AH_OFF 0
#define AL_OFF (128 * ALD)                       // 5120
#define BH_OFF (2 * 128 * ALD)                   // 10240
#define BL_OFF (2 * 128 * ALD + 32 * BLD)        // 14592
#define STAGE_EL (2 * 128 * ALD + 2 * 32 * BLD)  // 18944 elems / stage
#define WG_SMEM (2 * STAGE_EL * 2)               // 75776 bytes

__global__ __launch_bounds__(256, 2)
void wmma_gemm(const __nv_bfloat16* __restrict__ Ah, const __nv_bfloat16* __restrict__ Al,
               const __nv_bfloat16* __restrict__ Bh, const __nv_bfloat16* __restrict__ Bl,
               float* __restrict__ C, int M, int N, int Kp, int ldc)
{
    extern __shared__ __align__(16) __nv_bfloat16 sm[];

    int tid = threadIdx.x;
    int wid = tid >> 5, lane = tid & 31;
    int wm = wid & 3, wn = wid >> 2;
    int brow = blockIdx.y * 128, bcol = blockIdx.x * 128;
    int ns = Kp >> 5;

    wmma::fragment<wmma::accumulator, 16, 16, 16, float> acc[2][4];
    #pragma unroll
    for (int i = 0; i < 2; i++)
        #pragma unroll
        for (int j = 0; j < 4; j++) wmma::fill_fragment(acc[i][j], 0.f);

    auto load_slab = [&](int k0, int buf) {
        __nv_bfloat16* base = sm + buf * STAGE_EL;
        #pragma unroll
        for (int q = 0; q < 4; q++) {
            int a = tid + (q << 8);                 // 0..1023
            int row = a >> 3, c3 = a & 7, part = c3 >> 2, seg = c3 & 3;
            int gm = brow + row;
            const __nv_bfloat16* srcb = part ? Al : Ah;
            const void* src = (gm < M) ? (const void*)(srcb + (size_t)gm * Kp + k0 + seg * 8)
                                       : (const void*)srcb;
            unsigned int dst = smem_u32(base + (part ? AL_OFF : AH_OFF) + row * ALD + seg * 8);
            cp_async16(dst, src, (gm < M) ? 16 : 0);
        }
        #pragma unroll
        for (int q = 0; q < 4; q++) {
            int b = tid + (q << 8);                 // 0..1023
            int k = b >> 5, c5 = b & 31, part = c5 >> 4, cs = c5 & 15;
            const __nv_bfloat16* srcb = part ? Bl : Bh;
            const void* src = srcb + (size_t)(k0 + k) * NP + bcol + cs * 8;  // NP-padded
            unsigned int dst = smem_u32(base + (part ? BL_OFF : BH_OFF) + k * BLD + cs * 8);
            cp_async16(dst, src, 16);
        }
        asm volatile("cp.async.commit_group;\n");
    };

    load_slab(0, 0);

    for (int it = 0; it < ns; it++) {
        int buf = it & 1;
        if (it + 1 < ns) {
            load_slab((it + 1) << 5, buf ^ 1);
            asm volatile("cp.async.wait_group 1;\n");
        } else {
            asm volatile("cp.async.wait_group 0;\n");
        }
        __syncthreads();

        __nv_bfloat16* base = sm + buf * STAGE_EL;
        #pragma unroll
        for (int ks = 0; ks < 2; ks++) {
            wmma::fragment<wmma::matrix_a, 16, 16, 16, __nv_bfloat16, wmma::row_major> ah[2], al[2];
            #pragma unroll
            for (int i = 0; i < 2; i++) {
                wmma::load_matrix_sync(ah[i], base + AH_OFF + (wm * 32 + i * 16) * ALD + ks * 16, ALD);
                wmma::load_matrix_sync(al[i], base + AL_OFF + (wm * 32 + i * 16) * ALD + ks * 16, ALD);
            }
            #pragma unroll
            for (int j = 0; j < 4; j++) {
                wmma::fragment<wmma::matrix_b, 16, 16, 16, __nv_bfloat16, wmma::row_major> bh, bl;
                wmma::load_matrix_sync(bh, base + BH_OFF + ks * 16 * BLD + wn * 64 + j * 16, BLD);
                wmma::load_matrix_sync(bl, base + BL_OFF + ks * 16 * BLD + wn * 64 + j * 16, BLD);
                #pragma unroll
                for (int i = 0; i < 2; i++) {
                    wmma::mma_sync(acc[i][j], ah[i], bh, acc[i][j]);
                    wmma::mma_sync(acc[i][j], ah[i], bl, acc[i][j]);
                    wmma::mma_sync(acc[i][j], al[i], bh, acc[i][j]);
                }
            }
        }
        __syncthreads();
    }

    // ---- epilogue ----
    if (brow + 128 <= M && bcol + 128 <= N) {
        #pragma unroll
        for (int i = 0; i < 2; i++)
            #pragma unroll
            for (int j = 0; j < 4; j++) {
                int gm0 = brow + wm * 32 + i * 16;
                int gn0 = bcol + wn * 64 + j * 16;
                wmma::store_matrix_sync(&C[(size_t)gm0 * ldc + gn0], acc[i][j], ldc,
                                        wmma::mem_row_major);
            }
    } else {
        float* stagep = (float*)sm + wid * 272;
        __syncthreads();
        #pragma unroll
        for (int i = 0; i < 2; i++)
            #pragma unroll
            for (int j = 0; j < 4; j++) {
                wmma::store_matrix_sync(stagep, acc[i][j], 16, wmma::mem_row_major);
                __syncwarp();
                int gm0 = brow + wm * 32 + i * 16;
                int gn0 = bcol + wn * 64 + j * 16;
                for (int e = lane; e < 256; e += 32) {
                    int r = e >> 4, c = e & 15;
                    int gm = gm0 + r, gn = gn0 + c;
                    if (gm < M && gn < N) C[(size_t)gm * ldc + gn] = stagep[r * 16 + c];
                }
                __syncwarp();
            }
    }
}

// ---------------- fp32 tiled SGEMM for the small FC head ----------------
template<bool RELU_OUT>
__global__ void sgemm_kernel(const float* __restrict__ A, const float* __restrict__ B,
                             const float* __restrict__ bias, float* __restrict__ C,
                             int M, int N, int K, int ldc)
{
    const int BM = 64, BN = 64, BK = 16;
    __shared__ float As[BK][BM + 1];
    __shared__ float Bs[BK][BN + 1];
    int tid = threadIdx.x;
    int tx = tid & 15, ty = tid >> 4;
    int brow = blockIdx.y * BM;
    int bcol = blockIdx.x * BN;

    float acc[4][4];
    #pragma unroll
    for (int i = 0; i < 4; i++)
        #pragma unroll
        for (int j = 0; j < 4; j++) acc[i][j] = 0.f;

    for (int k0 = 0; k0 < K; k0 += BK) {
        #pragma unroll
        for (int i = 0; i < 4; i++) {
            int idx = tid + i * 256;
            int m = idx >> 4, k = idx & 15;
            int gm = brow + m, gk = k0 + k;
            As[k][m] = (gm < M && gk < K) ? A[(size_t)gm * K + gk] : 0.f;
        }
        #pragma unroll
        for (int i = 0; i < 4; i++) {
            int idx = tid + i * 256;
            int k = idx >> 6, n = idx & 63;
            int gk = k0 + k, gn = bcol + n;
            Bs[k][n] = (gk < K && gn < N) ? B[(size_t)gk * N + gn] : 0.f;
        }
        __syncthreads();
        #pragma unroll
        for (int kk = 0; kk < BK; kk++) {
            float a[4], b[4];
            #pragma unroll
            for (int i = 0; i < 4; i++) a[i] = As[kk][ty * 4 + i];
            #pragma unroll
            for (int j = 0; j < 4; j++) b[j] = Bs[kk][tx * 4 + j];
            #pragma unroll
            for (int i = 0; i < 4; i++)
                #pragma unroll
                for (int j = 0; j < 4; j++) acc[i][j] += a[i] * b[j];
        }
        __syncthreads();
    }
    #pragma unroll
    for (int i = 0; i < 4; i++) {
        int gm = brow + ty * 4 + i;
        if (gm >= M) continue;
        #pragma unroll
        for (int j = 0; j < 4; j++) {
            int gn = bcol + tx * 4 + j;
            if (gn >= N) continue;
            float v = acc[i][j] + (bias ? bias[gn] : 0.f);
            if (RELU_OUT) v = fmaxf(v, 0.f);
            C[(size_t)gm * ldc + gn] = v;
        }
    }
}

// ---------------- attention logits: warp per node, coalesced ----------------
__global__ __launch_bounds__(256)
void k_compute_a(const float* __restrict__ att_src, const float* __restrict__ att_dst) {
    __shared__ float ws[CC], wd[CC];
    for (int i = threadIdx.x; i < CC; i += 256) { ws[i] = att_src[i]; wd[i] = att_dst[i]; }
    __syncthreads();
    int warp = threadIdx.x >> 5, lane = threadIdx.x & 31;
    int n = blockIdx.x * 8 + warp;
    if (n >= NN) return;
    const float* row = g_bufA + (size_t)n * CC;
    #pragma unroll
    for (int h = 0; h < NH; h++) {
        int base = h * FD;
        float s = 0.f, d = 0.f;
        for (int f = lane; f < FD; f += 32) {
            float v = row[base + f];
            s += v * ws[base + f];
            d += v * wd[base + f];
        }
        #pragma unroll
        for (int o = 16; o > 0; o >>= 1) {
            s += __shfl_down_sync(0xffffffffu, s, o);
            d += __shfl_down_sync(0xffffffffu, d, o);
        }
        if (lane == 0) { g_as[n * NH + h] = s; g_ad[n * NH + h] = d; }
    }
}

// ---------------- fused GAT gather: one warp per dst; float4 rows; emits bf16 hi/lo ----------------
__global__ __launch_bounds__(256)
void k_gat_gather(const float* __restrict__ bias) {
    int w = (blockIdx.x * blockDim.x + threadIdx.x) >> 5;
    if (w >= NN) return;
    int lane = threadIdx.x & 31;
    int beg = g_off[w], end = g_off[w + 1];

    float ad = (lane < NH) ? g_ad[w * NH + lane] : 0.f;

    // pass 1: online softmax (lanes 0..NH-1 own one head each)
    float m = -1e30f, ssum = 0.f;
    for (int j = beg; j < end; j++) {
        int s = g_srccsr[j];
        if (lane < NH) {
            float e = g_as[s * NH + lane] + ad;
            e = (e > 0.f) ? e : 0.2f * e;
            float mn = fmaxf(m, e);
            ssum = ssum * expf(m - mn) + expf(e - mn);
            m = mn;
        }
    }
    float inv = 1.f / (ssum + 1e-16f);

    // precompute per-element head index (loop-invariant)
    int hidx[7][4];
    #pragma unroll
    for (int j = 0; j < 7; j++)
        #pragma unroll
        for (int c = 0; c < 4; c++) {
            int f = 4 * (lane + (j << 5)) + c;
            hidx[j][c] = (f < CC ? f : CC - 1) / FD;
        }

    // pass 2: weighted accumulation; lane owns float4 q = lane + 32*j
    float4 acc4[7];
    #pragma unroll
    for (int j = 0; j < 7; j++) acc4[j] = make_float4(0.f, 0.f, 0.f, 0.f);

    for (int j = beg; j < end; j++) {
        int s = g_srccsr[j];
        float alpha = 0.f;
        if (lane < NH) {
            float e = g_as[s * NH + lane] + ad;
            e = (e > 0.f) ? e : 0.2f * e;
            alpha = expf(e - m) * inv;
        }
        const float4* row4 = (const float4*)(g_bufA + (size_t)s * CC);
        #pragma unroll
        for (int i = 0; i < 7; i++) {
            float a0 = __shfl_sync(0xffffffffu, alpha, hidx[i][0]);
            float a1 = __shfl_sync(0xffffffffu, alpha, hidx[i][1]);
            float a2 = __shfl_sync(0xffffffffu, alpha, hidx[i][2]);
            float a3 = __shfl_sync(0xffffffffu, alpha, hidx[i][3]);
            int q = lane + (i << 5);
            if (q < CC / 4) {
                float4 v = row4[q];
                acc4[i].x += v.x * a0;
                acc4[i].y += v.y * a1;
                acc4[i].z += v.z * a2;
                acc4[i].w += v.w * a3;
            }
        }
    }
    // fused epilogue: relu(gat_out + bias) -> split bf16 hi/lo (row stride KP2)
    #pragma unroll
    for (int i = 0; i < 7; i++) {
        int q = lane + (i << 5);
        if (q < CC / 4) {
            int f0 = q * 4;
            float vv[4] = {acc4[i].x, acc4[i].y, acc4[i].z, acc4[i].w};
            #pragma unroll
            for (int c = 0; c < 4; c++) {
                float v = fmaxf(vv[c] + bias[f0 + c], 0.f);
                __nv_bfloat16 hi = __float2bfloat16(v);
                g_Ah[(size_t)w * KP2 + f0 + c] = hi;
                g_Al[(size_t)w * KP2 + f0 + c] = __float2bfloat16(v - __bfloat162float(hi));
            }
        }
    }
    // zero-fill K padding [780, 800)
    if (lane < KP2 - CC) {
        int f = CC + lane;
        g_Ah[(size_t)w * KP2 + f] = __float2bfloat16(0.f);
        g_Al[(size_t)w * KP2 + f] = __float2bfloat16(0.f);
    }
}

// ---------------- fused GCN gather: one warp per dst node, float4 ----------------
__global__ __launch_bounds__(256)
void k_gcn_gather(const float* __restrict__ bias) {
    int w = (blockIdx.x * blockDim.x + threadIdx.x) >> 5;
    if (w >= NN) return;
    int lane = threadIdx.x & 31;
    int beg = g_off[w], end = g_off[w + 1];
    float dv = g_dinv[w];

    float4 acc4[7];
    #pragma unroll
    for (int i = 0; i < 7; i++) acc4[i] = make_float4(0.f, 0.f, 0.f, 0.f);

    for (int j = beg; j < end; j++) {
        int s = g_srccsr[j];
        float nr = g_dinv[s] * dv;
        const float4* row4 = (const float4*)(g_bufA + (size_t)s * CC);
        #pragma unroll
        for (int i = 0; i < 7; i++) {
            int q = lane + (i << 5);
            if (q < CC / 4) {
                float4 v = row4[q];
                acc4[i].x += v.x * nr;
                acc4[i].y += v.y * nr;
                acc4[i].z += v.z * nr;
                acc4[i].w += v.w * nr;
            }
        }
    }
    const float4* bias4 = (const float4*)bias;
    float4* out4 = (float4*)(g_bufB + (size_t)w * CC);
    #pragma unroll
    for (int i = 0; i < 7; i++) {
        int q = lane + (i << 5);
        if (q < CC / 4) {
            float4 b = bias4[q];
            float4 o;
            o.x = acc4[i].x + b.x;
            o.y = acc4[i].y + b.y;
            o.z = acc4[i].z + b.z;
            o.w = acc4[i].w + b.w;
            out4[q] = o;
        }
    }
}

// ---------------- pooling (batch sorted -> contiguous ranges) ----------------
__global__ void k_pool2() {
    int b = blockIdx.y;
    int f = blockIdx.x * 256 + threadIdx.x;
    if (f >= CC) return;
    int s = g_bstart[b], e = g_bstart[b + 1];
    float mx = 0.f, sm = 0.f;
    for (int n = s; n < e; n++) {
        float v = fmaxf(g_bufB[(size_t)n * CC + f], 0.f);   // relu(gcn_out)
        mx = fmaxf(mx, v);
        sm += v;
    }
    g_g[b * 1560 + f] = mx;
    g_g[b * 1560 + 780 + f] = sm / fmaxf((float)(e - s), 1.f);
}

// ---------------- protein branches ----------------
__global__ void k_conv2(const int* __restrict__ t2, const float* __restrict__ emb,
                        const float* __restrict__ Wc2, const float* __restrict__ bc2)
{
    __shared__ float wag[26 * 256];
    int b = blockIdx.x;
    int tid = threadIdx.x;
    for (int v = 0; v < 26; v++) wag[v * 256 + tid] = 0.f;
    __syncthreads();
    int o = tid >> 3, k = tid & 7;
    const float* wcol = &Wc2[o * 8000 + k];
    const int* t2b = &t2[b * 1000];
    for (int i = 0; i < 1000; i++) {
        int v = t2b[i];
        wag[v * 256 + tid] += wcol[i * 8];
    }
    __syncthreads();
    for (int j = tid; j < 32 * 121; j += 256) {
        int oo = j / 121, l = j % 121;
        float acc = bc2[oo];
        for (int v = 0; v < 26; v++) {
            const float* wa = &wag[v * 256 + oo * 8];
            const float* er = &emb[v * 128 + l];
            #pragma unroll
            for (int kk = 0; kk < 8; kk++) acc += wa[kk] * er[kk];
        }
        g_xt2c[b * 3872 + j] = acc;
    }
}

__global__ void k_conv1(const float* __restrict__ t1, const float* __restrict__ Wc1,
                        const float* __restrict__ bc1)
{
    int b = blockIdx.x;
    int tid = threadIdx.x;
    int o = tid / 17, l = tid % 17;
    float acc = bc1[o];
    for (int i = 0; i < 20; i++) {
        const float* xr = &t1[b * 480 + i * 24 + l];
        const float* wr = &Wc1[o * 160 + i * 8];
        #pragma unroll
        for (int k = 0; k < 8; k++) acc += xr[k] * wr[k];
    }
    g_xt1c[b * 544 + tid] = acc;
}

// ---------------- launch ----------------
static inline dim3 gemm_grid(int M, int N) {
    return dim3((N + 63) / 64, (M + 63) / 64);
}

extern "C" void kernel_launch(void* const* d_in, const int* in_sizes, int n_in,
                              void* d_out, int out_size)
{
    const float* x       = (const float*)d_in[0];
    const int*   ei      = (const int*)  d_in[1];
    const int*   batch   = (const int*)  d_in[2];
    const float* target1 = (const float*)d_in[3];
    const int*   target2 = (const int*)  d_in[4];
    const float* W_gat   = (const float*)d_in[5];
    const float* att_src = (const float*)d_in[6];
    const float* att_dst = (const float*)d_in[7];
    const float* b_gat   = (const float*)d_in[8];
    const float* W_gcn   = (const float*)d_in[9];
    const float* b_gcn   = (const float*)d_in[10];
    const float* W_fcg1  = (const float*)d_in[11];
    const float* b_fcg1  = (const float*)d_in[12];
    const float* W_fcg2  = (const float*)d_in[13];
    const float* b_fcg2  = (const float*)d_in[14];
    const float* emb     = (const float*)d_in[15];
    const float* Wc2     = (const float*)d_in[16];
    const float* bc2     = (const float*)d_in[17];
    const float* W_fc2xt = (const float*)d_in[18];
    const float* b_fc2xt = (const float*)d_in[19];
    const float* Wc1     = (const float*)d_in[20];
    const float* bc1     = (const float*)d_in[21];
    const float* W_fc1xt = (const float*)d_in[22];
    const float* b_fc1xt = (const float*)d_in[23];
    const float* W_fc1   = (const float*)d_in[24];
    const float* b_fc1   = (const float*)d_in[25];
    const float* W_fc2   = (const float*)d_in[26];
    const float* b_fc2   = (const float*)d_in[27];
    const float* W_out   = (const float*)d_in[28];
    const float* b_out   = (const float*)d_in[29];
    float* out = (float*)d_out;

    int E0 = in_sizes[1] / 2;           // 150000
    int E  = E0 + NN;                   // + self loops

    // one-time host-side setup (no device allocations)
    static cudaStream_t s2 = nullptr, s3 = nullptr;
    static cudaEvent_t evFork = nullptr, evCsr = nullptr, evB2 = nullptr, evXt = nullptr;
    if (!s2) {
        cudaStreamCreateWithFlags(&s2, cudaStreamNonBlocking);
        cudaStreamCreateWithFlags(&s3, cudaStreamNonBlocking);
        cudaEventCreateWithFlags(&evFork, cudaEventDisableTiming);
        cudaEventCreateWithFlags(&evCsr,  cudaEventDisableTiming);
        cudaEventCreateWithFlags(&evB2,   cudaEventDisableTiming);
        cudaEventCreateWithFlags(&evXt,   cudaEventDisableTiming);
        cudaFuncSetAttribute(wmma_gemm, cudaFuncAttributeMaxDynamicSharedMemorySize, WG_SMEM);
    }

    float *bufA, *pg, *pt1, *pxc, *pxt2c, *pxt1c, *pf1, *pf2;
    __nv_bfloat16 *pAh, *pAl, *pBh1, *pBl1, *pBh2, *pBl2;
    cudaGetSymbolAddress((void**)&bufA,  g_bufA);
    cudaGetSymbolAddress((void**)&pAh,   g_Ah);
    cudaGetSymbolAddress((void**)&pAl,   g_Al);
    cudaGetSymbolAddress((void**)&pBh1,  g_Bh1);
    cudaGetSymbolAddress((void**)&pBl1,  g_Bl1);
    cudaGetSymbolAddress((void**)&pBh2,  g_Bh2);
    cudaGetSymbolAddress((void**)&pBl2,  g_Bl2);
    cudaGetSymbolAddress((void**)&pg,    g_g);
    cudaGetSymbolAddress((void**)&pt1,   g_t1);
    cudaGetSymbolAddress((void**)&pxc,   g_xc);
    cudaGetSymbolAddress((void**)&pxt2c, g_xt2c);
    cudaGetSymbolAddress((void**)&pxt1c, g_xt1c);
    cudaGetSymbolAddress((void**)&pf1,   g_f1);
    cudaGetSymbolAddress((void**)&pf2,   g_f2);

    dim3 wg_grid(7, (NN + 127) / 128);   // N tiles x M tiles

    // ---- fork ----
    cudaEventRecord(evFork, 0);
    cudaStreamWaitEvent(s2, evFork, 0);
    cudaStreamWaitEvent(s3, evFork, 0);

    // ---- stream s2: CSR chain + batch boundaries (independent of GEMM1) ----
    k_zero_deg<<<(NN + 255) / 256, 256, 0, s2>>>();
    k_count<<<(E + 255) / 256, 256, 0, s2>>>(ei, E0, E);
    k_scan1<<<NBLK, 1024, 0, s2>>>();
    k_scan2<<<1, 64, 0, s2>>>();
    k_scan3<<<(NN + 255) / 256, 256, 0, s2>>>();
    k_fillcsr<<<(E + 255) / 256, 256, 0, s2>>>(ei, E0, E);
    k_bstart<<<(NN + 255) / 256, 256, 0, s2>>>(batch);
    cudaEventRecord(evCsr, s2);

    // ---- stream s3: GEMM2 B-conversion + protein branch ----
    {
        size_t nb2 = (size_t)KP2 * NP;
        k_convB<<<(int)((nb2 + 255) / 256), 256, 0, s3>>>(W_gcn, CC, CC, KP2, pBh2, pBl2);
        cudaEventRecord(evB2, s3);
        k_conv2<<<NB, 256, 0, s3>>>(target2, emb, Wc2, bc2);
        sgemm_kernel<false><<<gemm_grid(NB, 128), 256, 0, s3>>>(pxt2c, W_fc2xt, b_fc2xt, pxc + 256, NB, 128, 3872, 384);
        k_conv1<<<NB, 544, 0, s3>>>(target1, Wc1, bc1);
        sgemm_kernel<false><<<gemm_grid(NB, 128), 256, 0, s3>>>(pxt1c, W_fc1xt, b_fc1xt, pxc + 128, NB, 128, 544, 384);
        cudaEventRecord(evXt, s3);
    }

    // ---- default stream: GNN critical path ----
    // h = x @ W_gat (split-bf16 wmma)
    {
        size_t na = (size_t)NN * KP1;
        k_convA<false><<<(int)((na + 255) / 256), 256>>>(x, NN, FD, KP1, pAh, pAl);
        size_t nb = (size_t)KP1 * NP;
        k_convB<<<(int)((nb + 255) / 256), 256>>>(W_gat, FD, CC, KP1, pBh1, pBl1);
        wmma_gemm<<<wg_grid, 256, WG_SMEM>>>(pAh, pAl, pBh1, pBl1, bufA, NN, CC, KP1, CC);
    }

    // GAT: logits + fused gather (needs CSR -> join s2)
    k_compute_a<<<(NN + 7) / 8, 256>>>(att_src, att_dst);
    cudaStreamWaitEvent(0, evCsr, 0);
    k_gat_gather<<<(NN * 32 + 255) / 256, 256>>>(b_gat);

    // hg = relu(gat_out) @ W_gcn (needs convB2 -> join s3's evB2)
    cudaStreamWaitEvent(0, evB2, 0);
    wmma_gemm<<<wg_grid, 256, WG_SMEM>>>(pAh, pAl, pBh2, pBl2, bufA, NN, CC, KP2, CC);

    // GCN gather + pooling
    k_gcn_gather<<<(NN * 32 + 255) / 256, 256>>>(b_gcn);
    k_pool2<<<dim3(4, NB), 256>>>();

    // graph MLP head
    sgemm_kernel<true ><<<gemm_grid(NB, 1500), 256>>>(pg,  W_fcg1, b_fcg1, pt1, NB, 1500, 1560, 1500);
    sgemm_kernel<false><<<gemm_grid(NB, 128),  256>>>(pt1, W_fcg2, b_fcg2, pxc + 0, NB, 128, 1500, 384);

    // final MLP (needs xt branches -> join s3)
    cudaStreamWaitEvent(0, evXt, 0);
    sgemm_kernel<true ><<<gemm_grid(NB, 1024), 256>>>(pxc, W_fc1, b_fc1, pf1, NB, 1024, 384, 1024);
    sgemm_kernel<true ><<<gemm_grid(NB, 512),  256>>>(pf1, W_fc2, b_fc2, pf2, NB, 512, 1024, 512);
    sgemm_kernel<false><<<gemm_grid(NB, 1),    256>>>(pf2, W_out, b_out, out, NB, 1, 512, 1);
}

// round 12
// speedup vs baseline: 2.9418x; 1.0335x over previous
#include <cuda_runtime.h>
#include <cuda_bf16.h>
#include <mma.h>
#include <math.h>
#include <cstdint>

using namespace nvcuda;

// ---------------- problem constants ----------------
#define NN 50000      // nodes
#define NB 128        // graphs / batch
#define NH 10         // heads
#define FD 78         // per-head feature
#define CC 780        // NH*FD
#define E0MAX 150000
#define EMAX  (E0MAX + NN)   // edges incl self loops
#define KP1 96               // GEMM1 K (78) padded to mult of 32
#define KP2 800              // GEMM2 K (780) padded to mult of 32
#define NP  896              // N padded (7*128) for B tiles
#define NBLK 49              // ceil(NN/1024)

// ---------------- scratch (device globals; no allocs) ----------------
__device__ float g_bufA[NN * CC];   // h = x@W_gat, later hg = relu(gat)@W_gcn
__device__ float g_bufB[NN * CC];   // gcn_out
__device__ __nv_bfloat16 g_Ah[NN * KP2];
__device__ __nv_bfloat16 g_Al[NN * KP2];
__device__ __nv_bfloat16 g_Bh1[KP1 * NP];   // GEMM1 B
__device__ __nv_bfloat16 g_Bl1[KP1 * NP];
__device__ __nv_bfloat16 g_Bh2[KP2 * NP];   // GEMM2 B
__device__ __nv_bfloat16 g_Bl2[KP2 * NP];
__device__ float g_wproj[FD * 20];  // [78][20]: cols 0..9 = W@att_src per head, 10..19 = W@att_dst
__device__ float g_asd[NN * 20];    // [n][20]: as (0..9), ad (10..19)
__device__ float g_m[NN * NH];
__device__ float g_inv[NN * NH];
__device__ int   g_degi[NN];
__device__ int   g_off[NN + 1];
__device__ int   g_cur[NN];
__device__ int   g_srccsr[EMAX];
__device__ float g_dinv[NN];
__device__ int   g_bstart[NB + 1];
__device__ int   g_bsum[64];
__device__ int   g_bsum2[64];
__device__ float g_g[NB * 1560];
__device__ float g_t1[NB * 1500];
__device__ float g_xc[NB * 384];
__device__ float g_xt2c[NB * 3872];
__device__ float g_xt1c[NB * 544];
__device__ float g_f1[NB * 1024];
__device__ float g_f2[NB * 512];

// ---------------- helpers ----------------
__device__ __forceinline__ void edge_sd(const int* ei, int E0, int e, int& s, int& d) {
    if (e < E0) { s = ei[e]; d = ei[E0 + e]; }
    else        { s = e - E0; d = e - E0; }
}

__device__ __forceinline__ void cp_async16(unsigned int smem, const void* gmem, int srcbytes) {
    asm volatile("cp.async.cg.shared.global [%0], [%1], 16, %2;\n"
                 :: "r"(smem), "l"(gmem), "r"(srcbytes));
}
__device__ __forceinline__ unsigned int smem_u32(const void* p) {
    return (unsigned int)__cvta_generic_to_shared(p);
}

// ---------------- CSR build ----------------
__global__ void k_zero_deg() {
    int i = blockIdx.x * blockDim.x + threadIdx.x;
    if (i < NN) g_degi[i] = 0;
}

__global__ void k_count(const int* __restrict__ ei, int E0, int E) {
    int e = blockIdx.x * blockDim.x + threadIdx.x;
    if (e >= E) return;
    int s, d; edge_sd(ei, E0, e, s, d);
    (void)s;
    atomicAdd(&g_degi[d], 1);
}

__global__ void k_scan1() {
    __shared__ int sh[1024];
    int tid = threadIdx.x;
    int i = blockIdx.x * 1024 + tid;
    int v = (i < NN) ? g_degi[i] : 0;
    sh[tid] = v;
    __syncthreads();
    #pragma unroll
    for (int o = 1; o < 1024; o <<= 1) {
        int t = (tid >= o) ? sh[tid - o] : 0;
        __syncthreads();
        sh[tid] += t;
        __syncthreads();
    }
    if (i < NN) g_off[i] = sh[tid] - v;      // block-local exclusive
    if (tid == 1023) g_bsum[blockIdx.x] = sh[1023];
}

__global__ void k_scan2() {
    __shared__ int sh[64];
    int t = threadIdx.x;
    int v = (t < NBLK) ? g_bsum[t] : 0;
    sh[t] = v;
    __syncthreads();
    #pragma unroll
    for (int o = 1; o < 64; o <<= 1) {
        int x = (t >= o) ? sh[t - o] : 0;
        __syncthreads();
        sh[t] += x;
        __syncthreads();
    }
    if (t < NBLK) g_bsum2[t] = sh[t] - v;    // exclusive
    if (t == 63) g_off[NN] = sh[63];         // total
}

// fused: finalize offsets + init cursors + dinv
__global__ void k_scan3() {
    int i = blockIdx.x * blockDim.x + threadIdx.x;
    if (i >= NN) return;
    int off = g_off[i] + g_bsum2[i >> 10];
    g_off[i] = off;
    g_cur[i] = off;
    float dg = (float)g_degi[i];
    g_dinv[i] = (dg > 0.f) ? rsqrtf(dg) : 0.f;
}

__global__ void k_fillcsr(const int* __restrict__ ei, int E0, int E) {
    int e = blockIdx.x * blockDim.x + threadIdx.x;
    if (e >= E) return;
    int s, d; edge_sd(ei, E0, e, s, d);
    int pos = atomicAdd(&g_cur[d], 1);
    g_srccsr[pos] = s;
}

__global__ void k_bstart(const int* __restrict__ batch) {
    int n = blockIdx.x * blockDim.x + threadIdx.x;
    if (n >= NN) return;
    int bn = batch[n];
    int bp = (n == 0) ? -1 : batch[n - 1];
    for (int g = bp + 1; g <= bn; g++) g_bstart[g] = n;
    if (n == NN - 1)
        for (int g = bn + 1; g <= NB; g++) g_bstart[g] = NN;
}

// ---------------- projected attention weights: wproj = W_gat (per-head) @ att ----------------
__global__ void k_wproj(const float* __restrict__ W, const float* __restrict__ att_src,
                        const float* __restrict__ att_dst) {
    int t = blockIdx.x * blockDim.x + threadIdx.x;
    if (t >= FD * 20) return;
    int i = t / 20, j = t % 20;
    int h = j % NH;
    const float* att = (j >= NH) ? att_dst : att_src;
    float s = 0.f;
    #pragma unroll 6
    for (int f = 0; f < FD; f++) s += W[(size_t)i * CC + h * FD + f] * att[h * FD + f];
    g_wproj[i * 20 + j] = s;
}

// ---------------- GAT softmax pass1: per-node online softmax over incident edges ----------------
__global__ __launch_bounds__(256)
void k_gat_pass1() {
    int w = (blockIdx.x * blockDim.x + threadIdx.x) >> 5;
    if (w >= NN) return;
    int lane = threadIdx.x & 31;
    int beg = g_off[w], end = g_off[w + 1];
    float ad = (lane < NH) ? g_asd[w * 20 + 10 + lane] : 0.f;
    float m = -1e30f, ssum = 0.f;
    for (int j = beg; j < end; j++) {
        int s = g_srccsr[j];
        if (lane < NH) {
            float e = g_asd[s * 20 + lane] + ad;
            e = (e > 0.f) ? e : 0.2f * e;
            float mn = fmaxf(m, e);
            ssum = ssum * expf(m - mn) + expf(e - mn);
            m = mn;
        }
    }
    if (lane < NH) {
        g_m[w * NH + lane] = m;
        g_inv[w * NH + lane] = 1.f / (ssum + 1e-16f);
    }
}

// ---------------- split-bf16 conversion ----------------
template<bool RELU>
__global__ void k_convA(const float* __restrict__ src, int M, int K, int Kp,
                        __nv_bfloat16* __restrict__ Ah, __nv_bfloat16* __restrict__ Al)
{
    size_t idx = (size_t)blockIdx.x * blockDim.x + threadIdx.x;
    if (idx >= (size_t)M * Kp) return;
    int c = (int)(idx % Kp);
    int r = (int)(idx / Kp);
    float v = 0.f;
    if (c < K) {
        v = src[(size_t)r * K + c];
        if (RELU) v = fmaxf(v, 0.f);
    }
    __nv_bfloat16 h = __float2bfloat16(v);
    Ah[idx] = h;
    Al[idx] = __float2bfloat16(v - __bfloat162float(h));
}

// B stored [k][NP] row-major, zero-padded columns/rows
__global__ void k_convB(const float* __restrict__ W, int K, int N, int Kp,
                        __nv_bfloat16* __restrict__ Bh, __nv_bfloat16* __restrict__ Bl)
{
    size_t idx = (size_t)blockIdx.x * blockDim.x + threadIdx.x;
    if (idx >= (size_t)Kp * NP) return;
    int n = (int)(idx % NP);
    int k = (int)(idx / NP);
    float v = (k < K && n < N) ? W[(size_t)k * N + n] : 0.f;
    __nv_bfloat16 h = __float2bfloat16(v);
    Bh[idx] = h;
    Bl[idx] = __float2bfloat16(v - __bfloat162float(h));
}

// ---------------- split-bf16 wmma GEMM v3 (BK=32, dynamic smem) ----------------
#define ALD 40      // A smem row stride (elems): 80B rows, conflict-free LDSM
#define BLD 136     // B smem row stride: 272B rows, conflict-free LDSM
#define AH_OFF 0
#define AL_OFF (128 * ALD)                       // 5120
#define BH_OFF (2 * 128 * ALD)                   // 10240
#define BL_OFF (2 * 128 * ALD + 32 * BLD)        // 14592
#define STAGE_EL (2 * 128 * ALD + 2 * 32 * BLD)  // 18944 elems / stage
#define WG_SMEM (2 * STAGE_EL * 2)               // 75776 bytes

__global__ __launch_bounds__(256, 2)
void wmma_gemm(const __nv_bfloat16* __restrict__ Ah, const __nv_bfloat16* __restrict__ Al,
               const __nv_bfloat16* __restrict__ Bh, const __nv_bfloat16* __restrict__ Bl,
               float* __restrict__ C, int M, int N, int Kp, int ldc)
{
    extern __shared__ __align__(16) __nv_bfloat16 sm[];

    int tid = threadIdx.x;
    int wid = tid >> 5, lane = tid & 31;
    int wm = wid & 3, wn = wid >> 2;
    int brow = blockIdx.y * 128, bcol = blockIdx.x * 128;
    int ns = Kp >> 5;

    wmma::fragment<wmma::accumulator, 16, 16, 16, float> acc[2][4];
    #pragma unroll
    for (int i = 0; i < 2; i++)
        #pragma unroll
        for (int j = 0; j < 4; j++) wmma::fill_fragment(acc[i][j], 0.f);

    auto load_slab = [&](int k0, int buf) {
        __nv_bfloat16* base = sm + buf * STAGE_EL;
        #pragma unroll
        for (int q = 0; q < 4; q++) {
            int a = tid + (q << 8);                 // 0..1023
            int row = a >> 3, c3 = a & 7, part = c3 >> 2, seg = c3 & 3;
            int gm = brow + row;
            const __nv_bfloat16* srcb = part ? Al : Ah;
            const void* src = (gm < M) ? (const void*)(srcb + (size_t)gm * Kp + k0 + seg * 8)
                                       : (const void*)srcb;
            unsigned int dst = smem_u32(base + (part ? AL_OFF : AH_OFF) + row * ALD + seg * 8);
            cp_async16(dst, src, (gm < M) ? 16 : 0);
        }
        #pragma unroll
        for (int q = 0; q < 4; q++) {
            int b = tid + (q << 8);                 // 0..1023
            int k = b >> 5, c5 = b & 31, part = c5 >> 4, cs = c5 & 15;
            const __nv_bfloat16* srcb = part ? Bl : Bh;
            const void* src = srcb + (size_t)(k0 + k) * NP + bcol + cs * 8;  // NP-padded
            unsigned int dst = smem_u32(base + (part ? BL_OFF : BH_OFF) + k * BLD + cs * 8);
            cp_async16(dst, src, 16);
        }
        asm volatile("cp.async.commit_group;\n");
    };

    load_slab(0, 0);

    for (int it = 0; it < ns; it++) {
        int buf = it & 1;
        if (it + 1 < ns) {
            load_slab((it + 1) << 5, buf ^ 1);
            asm volatile("cp.async.wait_group 1;\n");
        } else {
            asm volatile("cp.async.wait_group 0;\n");
        }
        __syncthreads();

        __nv_bfloat16* base = sm + buf * STAGE_EL;
        #pragma unroll
        for (int ks = 0; ks < 2; ks++) {
            wmma::fragment<wmma::matrix_a, 16, 16, 16, __nv_bfloat16, wmma::row_major> ah[2], al[2];
            #pragma unroll
            for (int i = 0; i < 2; i++) {
                wmma::load_matrix_sync(ah[i], base + AH_OFF + (wm * 32 + i * 16) * ALD + ks * 16, ALD);
                wmma::load_matrix_sync(al[i], base + AL_OFF + (wm * 32 + i * 16) * ALD + ks * 16, ALD);
            }
            #pragma unroll
            for (int j = 0; j < 4; j++) {
                wmma::fragment<wmma::matrix_b, 16, 16, 16, __nv_bfloat16, wmma::row_major> bh, bl;
                wmma::load_matrix_sync(bh, base + BH_OFF + ks * 16 * BLD + wn * 64 + j * 16, BLD);
                wmma::load_matrix_sync(bl, base + BL_OFF + ks * 16 * BLD + wn * 64 + j * 16, BLD);
                #pragma unroll
                for (int i = 0; i < 2; i++) {
                    wmma::mma_sync(acc[i][j], ah[i], bh, acc[i][j]);
                    wmma::mma_sync(acc[i][j], ah[i], bl, acc[i][j]);
                    wmma::mma_sync(acc[i][j], al[i], bh, acc[i][j]);
                }
            }
        }
        __syncthreads();
    }

    // ---- epilogue ----
    if (brow + 128 <= M && bcol + 128 <= N) {
        #pragma unroll
        for (int i = 0; i < 2; i++)
            #pragma unroll
            for (int j = 0; j < 4; j++) {
                int gm0 = brow + wm * 32 + i * 16;
                int gn0 = bcol + wn * 64 + j * 16;
                wmma::store_matrix_sync(&C[(size_t)gm0 * ldc + gn0], acc[i][j], ldc,
                                        wmma::mem_row_major);
            }
    } else {
        float* stagep = (float*)sm + wid * 272;
        __syncthreads();
        #pragma unroll
        for (int i = 0; i < 2; i++)
            #pragma unroll
            for (int j = 0; j < 4; j++) {
                wmma::store_matrix_sync(stagep, acc[i][j], 16, wmma::mem_row_major);
                __syncwarp();
                int gm0 = brow + wm * 32 + i * 16;
                int gn0 = bcol + wn * 64 + j * 16;
                for (int e = lane; e < 256; e += 32) {
                    int r = e >> 4, c = e & 15;
                    int gm = gm0 + r, gn = gn0 + c;
                    if (gm < M && gn < N) C[(size_t)gm * ldc + gn] = stagep[r * 16 + c];
                }
                __syncwarp();
            }
    }
}

// ---------------- fp32 tiled SGEMM for the small FC head ----------------
template<bool RELU_OUT>
__global__ void sgemm_kernel(const float* __restrict__ A, const float* __restrict__ B,
                             const float* __restrict__ bias, float* __restrict__ C,
                             int M, int N, int K, int ldc)
{
    const int BM = 64, BN = 64, BK = 16;
    __shared__ float As[BK][BM + 1];
    __shared__ float Bs[BK][BN + 1];
    int tid = threadIdx.x;
    int tx = tid & 15, ty = tid >> 4;
    int brow = blockIdx.y * BM;
    int bcol = blockIdx.x * BN;

    float acc[4][4];
    #pragma unroll
    for (int i = 0; i < 4; i++)
        #pragma unroll
        for (int j = 0; j < 4; j++) acc[i][j] = 0.f;

    for (int k0 = 0; k0 < K; k0 += BK) {
        #pragma unroll
        for (int i = 0; i < 4; i++) {
            int idx = tid + i * 256;
            int m = idx >> 4, k = idx & 15;
            int gm = brow + m, gk = k0 + k;
            As[k][m] = (gm < M && gk < K) ? A[(size_t)gm * K + gk] : 0.f;
        }
        #pragma unroll
        for (int i = 0; i < 4; i++) {
            int idx = tid + i * 256;
            int k = idx >> 6, n = idx & 63;
            int gk = k0 + k, gn = bcol + n;
            Bs[k][n] = (gk < K && gn < N) ? B[(size_t)gk * N + gn] : 0.f;
        }
        __syncthreads();
        #pragma unroll
        for (int kk = 0; kk < BK; kk++) {
            float a[4], b[4];
            #pragma unroll
            for (int i = 0; i < 4; i++) a[i] = As[kk][ty * 4 + i];
            #pragma unroll
            for (int j = 0; j < 4; j++) b[j] = Bs[kk][tx * 4 + j];
            #pragma unroll
            for (int i = 0; i < 4; i++)
                #pragma unroll
                for (int j = 0; j < 4; j++) acc[i][j] += a[i] * b[j];
        }
        __syncthreads();
    }
    #pragma unroll
    for (int i = 0; i < 4; i++) {
        int gm = brow + ty * 4 + i;
        if (gm >= M) continue;
        #pragma unroll
        for (int j = 0; j < 4; j++) {
            int gn = bcol + tx * 4 + j;
            if (gn >= N) continue;
            float v = acc[i][j] + (bias ? bias[gn] : 0.f);
            if (RELU_OUT) v = fmaxf(v, 0.f);
            C[(size_t)gm * ldc + gn] = v;
        }
    }
}

// ---------------- GAT pass2: weighted accumulation; emits relu'd bf16 hi/lo ----------------
__global__ __launch_bounds__(256)
void k_gat_pass2(const float* __restrict__ bias) {
    int w = (blockIdx.x * blockDim.x + threadIdx.x) >> 5;
    if (w >= NN) return;
    int lane = threadIdx.x & 31;
    int beg = g_off[w], end = g_off[w + 1];

    float ad = 0.f, m = 0.f, inv = 0.f;
    if (lane < NH) {
        ad  = g_asd[w * 20 + 10 + lane];
        m   = g_m[w * NH + lane];
        inv = g_inv[w * NH + lane];
    }

    // precompute per-element head index (loop-invariant)
    int hidx[7][4];
    #pragma unroll
    for (int j = 0; j < 7; j++)
        #pragma unroll
        for (int c = 0; c < 4; c++) {
            int f = 4 * (lane + (j << 5)) + c;
            hidx[j][c] = (f < CC ? f : CC - 1) / FD;
        }

    float4 acc4[7];
    #pragma unroll
    for (int j = 0; j < 7; j++) acc4[j] = make_float4(0.f, 0.f, 0.f, 0.f);

    for (int j = beg; j < end; j++) {
        int s = g_srccsr[j];
        float alpha = 0.f;
        if (lane < NH) {
            float e = g_asd[s * 20 + lane] + ad;
            e = (e > 0.f) ? e : 0.2f * e;
            alpha = expf(e - m) * inv;
        }
        const float4* row4 = (const float4*)(g_bufA + (size_t)s * CC);
        #pragma unroll
        for (int i = 0; i < 7; i++) {
            float a0 = __shfl_sync(0xffffffffu, alpha, hidx[i][0]);
            float a1 = __shfl_sync(0xffffffffu, alpha, hidx[i][1]);
            float a2 = __shfl_sync(0xffffffffu, alpha, hidx[i][2]);
            float a3 = __shfl_sync(0xffffffffu, alpha, hidx[i][3]);
            int q = lane + (i << 5);
            if (q < CC / 4) {
                float4 v = row4[q];
                acc4[i].x += v.x * a0;
                acc4[i].y += v.y * a1;
                acc4[i].z += v.z * a2;
                acc4[i].w += v.w * a3;
            }
        }
    }
    // fused epilogue: relu(gat_out + bias) -> split bf16 hi/lo (row stride KP2)
    #pragma unroll
    for (int i = 0; i < 7; i++) {
        int q = lane + (i << 5);
        if (q < CC / 4) {
            int f0 = q * 4;
            float vv[4] = {acc4[i].x, acc4[i].y, acc4[i].z, acc4[i].w};
            #pragma unroll
            for (int c = 0; c < 4; c++) {
                float v = fmaxf(vv[c] + bias[f0 + c], 0.f);
                __nv_bfloat16 hi = __float2bfloat16(v);
                g_Ah[(size_t)w * KP2 + f0 + c] = hi;
                g_Al[(size_t)w * KP2 + f0 + c] = __float2bfloat16(v - __bfloat162float(hi));
            }
        }
    }
    // zero-fill K padding [780, 800)
    if (lane < KP2 - CC) {
        int f = CC + lane;
        g_Ah[(size_t)w * KP2 + f] = __float2bfloat16(0.f);
        g_Al[(size_t)w * KP2 + f] = __float2bfloat16(0.f);
    }
}

// ---------------- fused GCN gather: one warp per dst node, float4 ----------------
__global__ __launch_bounds__(256)
void k_gcn_gather(const float* __restrict__ bias) {
    int w = (blockIdx.x * blockDim.x + threadIdx.x) >> 5;
    if (w >= NN) return;
    int lane = threadIdx.x & 31;
    int beg = g_off[w], end = g_off[w + 1];
    float dv = g_dinv[w];

    float4 acc4[7];
    #pragma unroll
    for (int i = 0; i < 7; i++) acc4[i] = make_float4(0.f, 0.f, 0.f, 0.f);

    for (int j = beg; j < end; j++) {
        int s = g_srccsr[j];
        float nr = g_dinv[s] * dv;
        const float4* row4 = (const float4*)(g_bufA + (size_t)s * CC);
        #pragma unroll
        for (int i = 0; i < 7; i++) {
            int q = lane + (i << 5);
            if (q < CC / 4) {
                float4 v = row4[q];
                acc4[i].x += v.x * nr;
                acc4[i].y += v.y * nr;
                acc4[i].z += v.z * nr;
                acc4[i].w += v.w * nr;
            }
        }
    }
    const float4* bias4 = (const float4*)bias;
    float4* out4 = (float4*)(g_bufB + (size_t)w * CC);
    #pragma unroll
    for (int i = 0; i < 7; i++) {
        int q = lane + (i << 5);
        if (q < CC / 4) {
            float4 b = bias4[q];
            float4 o;
            o.x = acc4[i].x + b.x;
            o.y = acc4[i].y + b.y;
            o.z = acc4[i].z + b.z;
            o.w = acc4[i].w + b.w;
            out4[q] = o;
        }
    }
}

// ---------------- pooling (batch sorted -> contiguous ranges) ----------------
__global__ void k_pool2() {
    int b = blockIdx.y;
    int f = blockIdx.x * 256 + threadIdx.x;
    if (f >= CC) return;
    int s = g_bstart[b], e = g_bstart[b + 1];
    float mx = 0.f, sm = 0.f;
    for (int n = s; n < e; n++) {
        float v = fmaxf(g_bufB[(size_t)n * CC + f], 0.f);   // relu(gcn_out)
        mx = fmaxf(mx, v);
        sm += v;
    }
    g_g[b * 1560 + f] = mx;
    g_g[b * 1560 + 780 + f] = sm / fmaxf((float)(e - s), 1.f);
}

// ---------------- protein branches ----------------
__global__ void k_conv2(const int* __restrict__ t2, const float* __restrict__ emb,
                        const float* __restrict__ Wc2, const float* __restrict__ bc2)
{
    __shared__ float wag[26 * 256];
    int b = blockIdx.x;
    int tid = threadIdx.x;
    for (int v = 0; v < 26; v++) wag[v * 256 + tid] = 0.f;
    __syncthreads();
    int o = tid >> 3, k = tid & 7;
    const float* wcol = &Wc2[o * 8000 + k];
    const int* t2b = &t2[b * 1000];
    for (int i = 0; i < 1000; i++) {
        int v = t2b[i];
        wag[v * 256 + tid] += wcol[i * 8];
    }
    __syncthreads();
    for (int j = tid; j < 32 * 121; j += 256) {
        int oo = j / 121, l = j % 121;
        float acc = bc2[oo];
        for (int v = 0; v < 26; v++) {
            const float* wa = &wag[v * 256 + oo * 8];
            const float* er = &emb[v * 128 + l];
            #pragma unroll
            for (int kk = 0; kk < 8; kk++) acc += wa[kk] * er[kk];
        }
        g_xt2c[b * 3872 + j] = acc;
    }
}

__global__ void k_conv1(const float* __restrict__ t1, const float* __restrict__ Wc1,
                        const float* __restrict__ bc1)
{
    int b = blockIdx.x;
    int tid = threadIdx.x;
    int o = tid / 17, l = tid % 17;
    float acc = bc1[o];
    for (int i = 0; i < 20; i++) {
        const float* xr = &t1[b * 480 + i * 24 + l];
        const float* wr = &Wc1[o * 160 + i * 8];
        #pragma unroll
        for (int k = 0; k < 8; k++) acc += xr[k] * wr[k];
    }
    g_xt1c[b * 544 + tid] = acc;
}

// ---------------- launch ----------------
static inline dim3 gemm_grid(int M, int N) {
    return dim3((N + 63) / 64, (M + 63) / 64);
}

extern "C" void kernel_launch(void* const* d_in, const int* in_sizes, int n_in,
                              void* d_out, int out_size)
{
    const float* x       = (const float*)d_in[0];
    const int*   ei      = (const int*)  d_in[1];
    const int*   batch   = (const int*)  d_in[2];
    const float* target1 = (const float*)d_in[3];
    const int*   target2 = (const int*)  d_in[4];
    const float* W_gat   = (const float*)d_in[5];
    const float* att_src = (const float*)d_in[6];
    const float* att_dst = (const float*)d_in[7];
    const float* b_gat   = (const float*)d_in[8];
    const float* W_gcn   = (const float*)d_in[9];
    const float* b_gcn   = (const float*)d_in[10];
    const float* W_fcg1  = (const float*)d_in[11];
    const float* b_fcg1  = (const float*)d_in[12];
    const float* W_fcg2  = (const float*)d_in[13];
    const float* b_fcg2  = (const float*)d_in[14];
    const float* emb     = (const float*)d_in[15];
    const float* Wc2     = (const float*)d_in[16];
    const float* bc2     = (const float*)d_in[17];
    const float* W_fc2xt = (const float*)d_in[18];
    const float* b_fc2xt = (const float*)d_in[19];
    const float* Wc1     = (const float*)d_in[20];
    const float* bc1     = (const float*)d_in[21];
    const float* W_fc1xt = (const float*)d_in[22];
    const float* b_fc1xt = (const float*)d_in[23];
    const float* W_fc1   = (const float*)d_in[24];
    const float* b_fc1   = (const float*)d_in[25];
    const float* W_fc2   = (const float*)d_in[26];
    const float* b_fc2   = (const float*)d_in[27];
    const float* W_out   = (const float*)d_in[28];
    const float* b_out   = (const float*)d_in[29];
    float* out = (float*)d_out;

    int E0 = in_sizes[1] / 2;           // 150000
    int E  = E0 + NN;                   // + self loops

    // one-time host-side setup (no device allocations)
    static cudaStream_t s2 = nullptr, s3 = nullptr;
    static cudaEvent_t evFork = nullptr, evP1 = nullptr, evB2 = nullptr, evXt = nullptr;
    if (!s2) {
        cudaStreamCreateWithFlags(&s2, cudaStreamNonBlocking);
        cudaStreamCreateWithFlags(&s3, cudaStreamNonBlocking);
        cudaEventCreateWithFlags(&evFork, cudaEventDisableTiming);
        cudaEventCreateWithFlags(&evP1,   cudaEventDisableTiming);
        cudaEventCreateWithFlags(&evB2,   cudaEventDisableTiming);
        cudaEventCreateWithFlags(&evXt,   cudaEventDisableTiming);
        cudaFuncSetAttribute(wmma_gemm, cudaFuncAttributeMaxDynamicSharedMemorySize, WG_SMEM);
    }

    float *bufA, *pg, *pt1, *pxc, *pxt2c, *pxt1c, *pf1, *pf2, *pwproj, *pasd;
    __nv_bfloat16 *pAh, *pAl, *pBh1, *pBl1, *pBh2, *pBl2;
    cudaGetSymbolAddress((void**)&bufA,  g_bufA);
    cudaGetSymbolAddress((void**)&pAh,   g_Ah);
    cudaGetSymbolAddress((void**)&pAl,   g_Al);
    cudaGetSymbolAddress((void**)&pBh1,  g_Bh1);
    cudaGetSymbolAddress((void**)&pBl1,  g_Bl1);
    cudaGetSymbolAddress((void**)&pBh2,  g_Bh2);
    cudaGetSymbolAddress((void**)&pBl2,  g_Bl2);
    cudaGetSymbolAddress((void**)&pwproj, g_wproj);
    cudaGetSymbolAddress((void**)&pasd,  g_asd);
    cudaGetSymbolAddress((void**)&pg,    g_g);
    cudaGetSymbolAddress((void**)&pt1,   g_t1);
    cudaGetSymbolAddress((void**)&pxc,   g_xc);
    cudaGetSymbolAddress((void**)&pxt2c, g_xt2c);
    cudaGetSymbolAddress((void**)&pxt1c, g_xt1c);
    cudaGetSymbolAddress((void**)&pf1,   g_f1);
    cudaGetSymbolAddress((void**)&pf2,   g_f2);

    dim3 wg_grid(7, (NN + 127) / 128);   // N tiles x M tiles

    // ---- fork ----
    cudaEventRecord(evFork, 0);
    cudaStreamWaitEvent(s2, evFork, 0);
    cudaStreamWaitEvent(s3, evFork, 0);

    // ---- stream s2: attention stats (wproj -> asd), CSR chain, softmax pass1 ----
    k_wproj<<<(FD * 20 + 255) / 256, 256, 0, s2>>>(W_gat, att_src, att_dst);
    sgemm_kernel<false><<<gemm_grid(NN, 20), 256, 0, s2>>>(x, pwproj, nullptr, pasd, NN, 20, FD, 20);
    k_zero_deg<<<(NN + 255) / 256, 256, 0, s2>>>();
    k_count<<<(E + 255) / 256, 256, 0, s2>>>(ei, E0, E);
    k_scan1<<<NBLK, 1024, 0, s2>>>();
    k_scan2<<<1, 64, 0, s2>>>();
    k_scan3<<<(NN + 255) / 256, 256, 0, s2>>>();
    k_fillcsr<<<(E + 255) / 256, 256, 0, s2>>>(ei, E0, E);
    k_bstart<<<(NN + 255) / 256, 256, 0, s2>>>(batch);
    k_gat_pass1<<<(NN * 32 + 255) / 256, 256, 0, s2>>>();
    cudaEventRecord(evP1, s2);

    // ---- stream s3: GEMM2 B-conversion + protein branch ----
    {
        size_t nb2 = (size_t)KP2 * NP;
        k_convB<<<(int)((nb2 + 255) / 256), 256, 0, s3>>>(W_gcn, CC, CC, KP2, pBh2, pBl2);
        cudaEventRecord(evB2, s3);
        k_conv2<<<NB, 256, 0, s3>>>(target2, emb, Wc2, bc2);
        sgemm_kernel<false><<<gemm_grid(NB, 128), 256, 0, s3>>>(pxt2c, W_fc2xt, b_fc2xt, pxc + 256, NB, 128, 3872, 384);
        k_conv1<<<NB, 544, 0, s3>>>(target1, Wc1, bc1);
        sgemm_kernel<false><<<gemm_grid(NB, 128), 256, 0, s3>>>(pxt1c, W_fc1xt, b_fc1xt, pxc + 128, NB, 128, 544, 384);
        cudaEventRecord(evXt, s3);
    }

    // ---- default stream: GNN critical path ----
    // h = x @ W_gat (split-bf16 wmma)
    {
        size_t na = (size_t)NN * KP1;
        k_convA<false><<<(int)((na + 255) / 256), 256>>>(x, NN, FD, KP1, pAh, pAl);
        size_t nb = (size_t)KP1 * NP;
        k_convB<<<(int)((nb + 255) / 256), 256>>>(W_gat, FD, CC, KP1, pBh1, pBl1);
        wmma_gemm<<<wg_grid, 256, WG_SMEM>>>(pAh, pAl, pBh1, pBl1, bufA, NN, CC, KP1, CC);
    }

    // GAT pass2 (needs h + CSR + softmax stats -> join s2)
    cudaStreamWaitEvent(0, evP1, 0);
    k_gat_pass2<<<(NN * 32 + 255) / 256, 256>>>(b_gat);

    // hg = relu(gat_out) @ W_gcn (needs convB2 -> join s3's evB2)
    cudaStreamWaitEvent(0, evB2, 0);
    wmma_gemm<<<wg_grid, 256, WG_SMEM>>>(pAh, pAl, pBh2, pBl2, bufA, NN, CC, KP2, CC);

    // GCN gather + pooling
    k_gcn_gather<<<(NN * 32 + 255) / 256, 256>>>(b_gcn);
    k_pool2<<<dim3(4, NB), 256>>>();

    // graph MLP head
    sgemm_kernel<true ><<<gemm_grid(NB, 1500), 256>>>(pg,  W_fcg1, b_fcg1, pt1, NB, 1500, 1560, 1500);
    sgemm_kernel<false><<<gemm_grid(NB, 128),  256>>>(pt1, W_fcg2, b_fcg2, pxc + 0, NB, 128, 1500, 384);

    // final MLP (needs xt branches -> join s3)
    cudaStreamWaitEvent(0, evXt, 0);
    sgemm_kernel<true ><<<gemm_grid(NB, 1024), 256>>>(pxc, W_fc1, b_fc1, pf1, NB, 1024, 384, 1024);
    sgemm_kernel<true ><<<gemm_grid(NB, 512),  256>>>(pf1, W_fc2, b_fc2, pf2, NB, 512, 1024, 512);
    sgemm_kernel<false><<<gemm_grid(NB, 1),    256>>>(pf2, W_out, b_out, out, NB, 1, 512, 1);
}